// round 10
// baseline (speedup 1.0000x reference)
#include <cuda_runtime.h>
#include <math.h>

#define NL     32
#define NB     128
#define NPQ    40
#define NTHR   1024
#define GRP    128      // threads per barrier group (4 warps)

typedef unsigned long long u64;

// ---------------------------------------------------------------------------
// gate tables.  bit position = 9 - wire.
// type: 0 = RY (PA = bit pos), 1 = CRX (PA = control bit, PB = target bit)
// ---------------------------------------------------------------------------
constexpr int G_TYPE[40] = {0,0,0,0,0,0,0,0,0,0, 1,1,1,1,1,1,1,1,1,1,
                            0,0,0,0,0,0,0,0,0,0, 1,1,1,1,1,1,1,1,1,1};
constexpr int G_PA[40]   = {9,8,7,6,5,4,3,2,1,0, 0,1,2,3,4,5,6,7,8,9,
                            9,8,7,6,5,4,3,2,1,0, 0,9,8,7,6,5,4,3,2,1};
constexpr int G_PB[40]   = {0,0,0,0,0,0,0,0,0,0, 9,0,1,2,3,4,5,6,7,8,
                            0,0,0,0,0,0,0,0,0,0, 1,0,9,8,7,6,5,4,3,2};

// ---------------------------------------------------------------------------
// f32x2 helpers
// ---------------------------------------------------------------------------
__device__ __forceinline__ u64 F2(float2 v) {
    u64 r; asm("mov.b64 %0, {%1,%2};" : "=l"(r) : "f"(v.x), "f"(v.y)); return r;
}
__device__ __forceinline__ float2 U2(u64 v) {
    float2 p; asm("mov.b64 {%0,%1}, %2;" : "=f"(p.x), "=f"(p.y) : "l"(v)); return p;
}
__device__ __forceinline__ u64 fma2(u64 a, u64 b, u64 c) {
    u64 d; asm("fma.rn.f32x2 %0, %1, %2, %3;" : "=l"(d) : "l"(a), "l"(b), "l"(c)); return d;
}
__device__ __forceinline__ u64 mul2(u64 a, u64 b) {
    u64 d; asm("mul.rn.f32x2 %0, %1, %2;" : "=l"(d) : "l"(a), "l"(b)); return d;
}
__device__ __forceinline__ u64 add2(u64 a, u64 b) {
    u64 d; asm("add.rn.f32x2 %0, %1, %2;" : "=l"(d) : "l"(a), "l"(b)); return d;
}
template<int M>
__device__ __forceinline__ u64 shfl2(u64 v) {
    float2 t = U2(v);
    t.x = __shfl_xor_sync(0xffffffffu, t.x, M);
    t.y = __shfl_xor_sync(0xffffffffu, t.y, M);
    return F2(t);
}
__device__ __forceinline__ u64 swap2(u64 v) {
    float2 t = U2(v);
    return F2(make_float2(t.y, t.x));
}
// named barrier over a 4-warp group (128 threads); ids 1..8 (disjoint from bar 0)
__device__ __forceinline__ void pairbar(int id) {
    asm volatile("bar.sync %0, 128;" :: "r"(id) : "memory");
}

// ---------------------------------------------------------------------------
// state: each PAIR of warps (w, w^1) holds one 1024-amp state.
//   amp = (wb<<9) | (pack<<8) | (v<<5) | lane ;  warp holds X[8], Y[8] u64
//   P<5 -> lane (shfl); 5<=P<8 -> v bit; P==8 -> pack (swap2); P==9 -> warp bit
// Exchange region: per-group 16KB slab.
// ---------------------------------------------------------------------------

template<int P>
__device__ __forceinline__ void ry_lane(u64 (&X)[8], u64 (&Y)[8], float c, float s, unsigned lane) {
    const float sg = ((lane >> P) & 1u) ? s : -s;
    const u64 cc = F2(make_float2(c, c)), sg2 = F2(make_float2(sg, sg));
#pragma unroll
    for (int v = 0; v < 8; ++v) {
        X[v] = fma2(sg2, shfl2<(1 << P)>(X[v]), mul2(cc, X[v]));
        Y[v] = fma2(sg2, shfl2<(1 << P)>(Y[v]), mul2(cc, Y[v]));
    }
}
template<int RB>
__device__ __forceinline__ void ry_reg(u64 (&X)[8], u64 (&Y)[8], float c, float s) {
    const u64 cc = F2(make_float2(c, c));
    const u64 sp = F2(make_float2(s, s)), sn = F2(make_float2(-s, -s));
#pragma unroll
    for (int v0 = 0; v0 < 8; ++v0) {
        if (v0 & (1 << RB)) continue;
        const int v1 = v0 | (1 << RB);
        u64 a0x = X[v0], a1x = X[v1], a0y = Y[v0], a1y = Y[v1];
        X[v0] = fma2(sn, a1x, mul2(cc, a0x));
        X[v1] = fma2(sp, a0x, mul2(cc, a1x));
        Y[v0] = fma2(sn, a1y, mul2(cc, a0y));
        Y[v1] = fma2(sp, a0y, mul2(cc, a1y));
    }
}
__device__ __forceinline__ void ry_pack(u64 (&X)[8], u64 (&Y)[8], float c, float s) {
    const u64 cc = F2(make_float2(c, c)), sv = F2(make_float2(-s, s));
#pragma unroll
    for (int v = 0; v < 8; ++v) {
        X[v] = fma2(sv, swap2(X[v]), mul2(cc, X[v]));
        Y[v] = fma2(sv, swap2(Y[v]), mul2(cc, Y[v]));
    }
}
// RY on warp bit: full exchange via 128-bit smem ops in the group slab
__device__ __forceinline__ void ry_warp(u64 (&X)[8], u64 (&Y)[8], float c, float s,
                                        ulonglong2* Eg, int gt, int pgt, int barid, int wb) {
#pragma unroll
    for (int i = 0; i < 4; ++i)
        Eg[i * GRP + gt] = make_ulonglong2(X[2 * i], X[2 * i + 1]);
#pragma unroll
    for (int i = 0; i < 4; ++i)
        Eg[(4 + i) * GRP + gt] = make_ulonglong2(Y[2 * i], Y[2 * i + 1]);
    pairbar(barid);
    const float sg = wb ? s : -s;
    const u64 sg2 = F2(make_float2(sg, sg)), cc = F2(make_float2(c, c));
#pragma unroll
    for (int i = 0; i < 4; ++i) {
        ulonglong2 p = Eg[i * GRP + pgt];
        X[2 * i]     = fma2(sg2, p.x, mul2(cc, X[2 * i]));
        X[2 * i + 1] = fma2(sg2, p.y, mul2(cc, X[2 * i + 1]));
    }
#pragma unroll
    for (int i = 0; i < 4; ++i) {
        ulonglong2 p = Eg[(4 + i) * GRP + pgt];
        Y[2 * i]     = fma2(sg2, p.x, mul2(cc, Y[2 * i]));
        Y[2 * i + 1] = fma2(sg2, p.y, mul2(cc, Y[2 * i + 1]));
    }
    pairbar(barid);
}
// CRX k=10: control = lane bit 0, target = warp bit.  Only odd lanes exchange.
__device__ __forceinline__ void crx10(u64 (&X)[8], u64 (&Y)[8], float c, float s,
                                      unsigned lane, ulonglong2* Eg, int gt, int pgt, int barid) {
    const bool act = (lane & 1u) != 0u;
    if (act) {
#pragma unroll
        for (int i = 0; i < 4; ++i)
            Eg[i * GRP + gt] = make_ulonglong2(X[2 * i], X[2 * i + 1]);
#pragma unroll
        for (int i = 0; i < 4; ++i)
            Eg[(4 + i) * GRP + gt] = make_ulonglong2(Y[2 * i], Y[2 * i + 1]);
    }
    pairbar(barid);
    if (act) {
        const u64 cc = F2(make_float2(c, c));
        const u64 sp = F2(make_float2(s, s)), sn = F2(make_float2(-s, -s));
#pragma unroll
        for (int i = 0; i < 4; ++i) {
            ulonglong2 py = Eg[(4 + i) * GRP + pgt];
            X[2 * i]     = fma2(sp, py.x, mul2(cc, X[2 * i]));
            X[2 * i + 1] = fma2(sp, py.y, mul2(cc, X[2 * i + 1]));
        }
#pragma unroll
        for (int i = 0; i < 4; ++i) {
            ulonglong2 px = Eg[i * GRP + pgt];
            Y[2 * i]     = fma2(sn, px.x, mul2(cc, Y[2 * i]));
            Y[2 * i + 1] = fma2(sn, px.y, mul2(cc, Y[2 * i + 1]));
        }
    }
    pairbar(barid);
}
// CRX k=10 with Y==0 everywhere (step-1 fast path): exchange X only.
__device__ __forceinline__ void crx10_y0(u64 (&X)[8], u64 (&Y)[8], float c, float s,
                                         unsigned lane, ulonglong2* Eg, int gt, int pgt, int barid) {
    const bool act = (lane & 1u) != 0u;
    if (act) {
#pragma unroll
        for (int i = 0; i < 4; ++i)
            Eg[i * GRP + gt] = make_ulonglong2(X[2 * i], X[2 * i + 1]);
    }
    pairbar(barid);
    if (act) {
        const u64 cc = F2(make_float2(c, c));
        const u64 sn = F2(make_float2(-s, -s));
#pragma unroll
        for (int i = 0; i < 4; ++i) {
            ulonglong2 px = Eg[i * GRP + pgt];
            Y[2 * i]     = mul2(sn, px.x);
            Y[2 * i + 1] = mul2(sn, px.y);
            X[2 * i]     = mul2(cc, X[2 * i]);
            X[2 * i + 1] = mul2(cc, X[2 * i + 1]);
        }
    }
    pairbar(barid);
}
// CRX k=32: control = pack bit (hi half), target = warp bit.  Exchange hi floats only.
__device__ __forceinline__ void crx32(u64 (&X)[8], u64 (&Y)[8], float c, float s,
                                      float* Fg, int gt, int pgt, int barid) {
#pragma unroll
    for (int i = 0; i < 8; ++i) Fg[i * GRP + gt] = U2(X[i]).y;
#pragma unroll
    for (int i = 0; i < 8; ++i) Fg[(8 + i) * GRP + gt] = U2(Y[i]).y;
    pairbar(barid);
#pragma unroll
    for (int i = 0; i < 8; ++i) {
        float pxh = Fg[i * GRP + pgt];
        float pyh = Fg[(8 + i) * GRP + pgt];
        float2 x = U2(X[i]), y = U2(Y[i]);
        x.y = fmaf(s, pyh, c * x.y);
        y.y = fmaf(-s, pxh, c * y.y);
        X[i] = F2(x); Y[i] = F2(y);
    }
    pairbar(barid);
}

// RX (warp-bit-controlled, executes locally on wb==1) on target B != 9
template<int B>
__device__ __forceinline__ void rx_local(u64 (&X)[8], u64 (&Y)[8], float c, float s) {
    const u64 ce2 = F2(make_float2(c, c));
    const u64 se2 = F2(make_float2(s, s)), sn2 = F2(make_float2(-s, -s));
    if constexpr (B < 5) {
#pragma unroll
        for (int v = 0; v < 8; ++v) {
            u64 px = shfl2<(1 << B)>(X[v]);
            u64 py = shfl2<(1 << B)>(Y[v]);
            X[v] = fma2(se2, py, mul2(ce2, X[v]));
            Y[v] = fma2(sn2, px, mul2(ce2, Y[v]));
        }
    } else if constexpr (B < 8) {
        constexpr int TB = 1 << (B - 5);
#pragma unroll
        for (int v0 = 0; v0 < 8; ++v0) {
            if (v0 & TB) continue;
            const int v1 = v0 | TB;
            u64 a0x = X[v0], a0y = Y[v0], a1x = X[v1], a1y = Y[v1];
            X[v0] = fma2(se2, a1y, mul2(ce2, a0x));
            Y[v0] = fma2(sn2, a1x, mul2(ce2, a0y));
            X[v1] = fma2(se2, a0y, mul2(ce2, a1x));
            Y[v1] = fma2(sn2, a0x, mul2(ce2, a1y));
        }
    } else {
#pragma unroll
        for (int v = 0; v < 8; ++v) {
            u64 sx = swap2(X[v]), sy = swap2(Y[v]);
            X[v] = fma2(se2, sy, mul2(ce2, X[v]));
            Y[v] = fma2(sn2, sx, mul2(ce2, Y[v]));
        }
    }
}

// CRX, control A != 9, target B != 9
template<int A, int B>
__device__ __forceinline__ void crx_gate(u64 (&X)[8], u64 (&Y)[8], float c, float s, unsigned lane) {
    float2 cef, sef;
    if constexpr (A < 5) {
        const int cb = (lane >> A) & 1u;
        const float ce = cb ? c : 1.0f, se = cb ? s : 0.0f;
        cef = make_float2(ce, ce); sef = make_float2(se, se);
    } else if constexpr (A == 8) {
        cef = make_float2(1.0f, c); sef = make_float2(0.0f, s);
    } else {
        cef = make_float2(c, c); sef = make_float2(s, s);
    }
    const u64 ce2 = F2(cef), se2 = F2(sef), sn2 = F2(make_float2(-sef.x, -sef.y));
    constexpr bool vctrl = (A >= 5 && A < 8);
    constexpr int CB = vctrl ? (1 << (A - 5)) : 0;

    if constexpr (B < 5) {
#pragma unroll
        for (int v = 0; v < 8; ++v) {
            if (vctrl && !(v & CB)) continue;
            u64 px = shfl2<(1 << B)>(X[v]);
            u64 py = shfl2<(1 << B)>(Y[v]);
            X[v] = fma2(se2, py, mul2(ce2, X[v]));
            Y[v] = fma2(sn2, px, mul2(ce2, Y[v]));
        }
    } else if constexpr (B < 8) {
        constexpr int TB = 1 << (B - 5);
#pragma unroll
        for (int v0 = 0; v0 < 8; ++v0) {
            if (v0 & TB) continue;
            if (vctrl && !(v0 & CB)) continue;
            const int v1 = v0 | TB;
            u64 a0x = X[v0], a0y = Y[v0], a1x = X[v1], a1y = Y[v1];
            X[v0] = fma2(se2, a1y, mul2(ce2, a0x));
            Y[v0] = fma2(sn2, a1x, mul2(ce2, a0y));
            X[v1] = fma2(se2, a0y, mul2(ce2, a1x));
            Y[v1] = fma2(sn2, a0x, mul2(ce2, a1y));
        }
    } else {
#pragma unroll
        for (int v = 0; v < 8; ++v) {
            if (vctrl && !(v & CB)) continue;
            u64 sx = swap2(X[v]), sy = swap2(Y[v]);
            X[v] = fma2(se2, sy, mul2(ce2, X[v]));
            Y[v] = fma2(sn2, sx, mul2(ce2, Y[v]));
        }
    }
}

template<int K>
__device__ __forceinline__ void do_gate(u64 (&X)[8], u64 (&Y)[8], const float* csl,
                                        unsigned lane, int wb,
                                        ulonglong2* Eg, float* Fg, int gt, int pgt, int barid) {
    const float c = csl[2 * K];
    const float s = csl[2 * K + 1];
    constexpr int A = G_PA[K], Bp = G_PB[K];
    if constexpr (K == 0 || K == 20) {
        ry_warp(X, Y, c, s, Eg, gt, pgt, barid, wb);
    } else if constexpr (K == 10) {
        crx10(X, Y, c, s, lane, Eg, gt, pgt, barid);
    } else if constexpr (K == 32) {
        crx32(X, Y, c, s, Fg, gt, pgt, barid);
    } else if constexpr (G_TYPE[K] == 1 && A == 9) {
        if (wb) rx_local<Bp>(X, Y, c, s);
    } else if constexpr (G_TYPE[K] == 0) {
        if constexpr (A == 8)      ry_pack(X, Y, c, s);
        else if constexpr (A >= 5) ry_reg<A - 5>(X, Y, c, s);
        else                       ry_lane<A>(X, Y, c, s, lane);
    } else {
        crx_gate<A, Bp>(X, Y, c, s, lane);
    }
}

template<int K, int KEND = 40>
__device__ __forceinline__ void run_gates(u64 (&X)[8], u64 (&Y)[8], const float* csl,
                                          unsigned lane, int wb,
                                          ulonglong2* Eg, float* Fg, int gt, int pgt, int barid) {
    if constexpr (K < KEND) {
        do_gate<K>(X, Y, csl, lane, wb, Eg, Fg, gt, pgt, barid);
        run_gates<K + 1, KEND>(X, Y, csl, lane, wb, Eg, Fg, gt, pgt, barid);
    }
}

// ---- step-1 shortcut: product state after the first RY layer (gates 0..9) ----
__device__ __forceinline__ void build_ry_product(u64 (&X)[8], u64 (&Y)[8],
                                                 const float* cs, unsigned lane, int wb) {
    float A = wb ? cs[1] : cs[0];                      // P=9, k=0
    A *= (lane & 1u)  ? cs[19] : cs[18];               // P=0, k=9
    A *= (lane & 2u)  ? cs[17] : cs[16];               // P=1, k=8
    A *= (lane & 4u)  ? cs[15] : cs[14];               // P=2, k=7
    A *= (lane & 8u)  ? cs[13] : cs[12];               // P=3, k=6
    A *= (lane & 16u) ? cs[11] : cs[10];               // P=4, k=5
    const float c4 = cs[8],  s4 = cs[9];               // P=5, k=4  (v bit 0)
    const float c3 = cs[6],  s3 = cs[7];               // P=6, k=3  (v bit 1)
    const float c2 = cs[4],  s2 = cs[5];               // P=7, k=2  (v bit 2)
    const float c1 = cs[2],  s1 = cs[3];               // P=8, k=1  (pack bit)
    const float a0 = c3 * c2, a1 = s3 * c2, a2 = c3 * s2, a3 = s3 * s2;
    float fv[8];
    fv[0] = c4 * a0; fv[1] = s4 * a0; fv[2] = c4 * a1; fv[3] = s4 * a1;
    fv[4] = c4 * a2; fv[5] = s4 * a2; fv[6] = c4 * a3; fv[7] = s4 * a3;
#pragma unroll
    for (int v = 0; v < 8; ++v) {
        const float g = A * fv[v];
        X[v] = F2(make_float2(g * c1, g * s1));
        Y[v] = 0ull;
    }
}

// ---- register-resident measurement helpers (per pair; wire = pair, P = 9-pair) --
template<int P>
__device__ __forceinline__ void meas_lane(const u64 (&X)[8], const u64 (&Y)[8], unsigned lane,
                                          u64& cr2, u64& ci2, u64& zz2) {
    const int bit = (lane >> P) & 1u;
    const u64 f02 = F2(bit ? make_float2(0.f, 0.f) : make_float2(1.f, 1.f));
    const u64 zs2 = F2(bit ? make_float2(-1.f, -1.f) : make_float2(1.f, 1.f));
    const u64 M1  = F2(make_float2(-1.f, -1.f));
#pragma unroll
    for (int v = 0; v < 8; ++v) {
        u64 px = shfl2<(1 << P)>(X[v]);
        u64 py = shfl2<(1 << P)>(Y[v]);
        u64 t1 = fma2(Y[v], py, mul2(X[v], px));                 // x*px + y*py
        cr2 = fma2(f02, t1, cr2);
        u64 t2 = fma2(X[v], py, mul2(mul2(Y[v], px), M1));       // x*py - y*px
        ci2 = fma2(f02, t2, ci2);
        u64 nn = fma2(Y[v], Y[v], mul2(X[v], X[v]));
        zz2 = fma2(zs2, nn, zz2);
    }
}
template<int RB>
__device__ __forceinline__ void meas_vbit(const u64 (&X)[8], const u64 (&Y)[8],
                                          u64& cr2, u64& ci2, u64& zz2) {
    const u64 M1 = F2(make_float2(-1.f, -1.f));
#pragma unroll
    for (int v0 = 0; v0 < 8; ++v0) {
        if (v0 & (1 << RB)) continue;
        const int v1 = v0 | (1 << RB);
        cr2 = add2(cr2, fma2(Y[v0], Y[v1], mul2(X[v0], X[v1])));
        ci2 = add2(ci2, fma2(X[v0], Y[v1], mul2(mul2(Y[v0], X[v1]), M1)));
        u64 n0 = fma2(Y[v0], Y[v0], mul2(X[v0], X[v0]));
        u64 n1 = fma2(Y[v1], Y[v1], mul2(X[v1], X[v1]));
        zz2 = add2(zz2, add2(n0, mul2(n1, M1)));
    }
}
__device__ __forceinline__ void meas_pack(const u64 (&X)[8], const u64 (&Y)[8],
                                          float& cr, float& ci, float& zz) {
#pragma unroll
    for (int v = 0; v < 8; ++v) {
        float2 x = U2(X[v]), y = U2(Y[v]);
        cr += x.x * x.y + y.x * y.y;
        ci += x.x * y.y - y.x * x.y;
        zz += (x.x * x.x + y.x * y.x) - (x.y * x.y + y.y * y.y);
    }
}

// ---------------------------------------------------------------------------
// smem layout (bytes):
//   [0,10240)      cs_s  2560 f
//   [10240,10560)  ffcs  80 f
//   [10560,10816)  lcu_s 32 f2
//   [10816,11072)  rsum  64 f  (norm partials; then measure partials 3/warp)
//   [11072, ...)   UNION:
//     GEMM:  emb_s 32*516 f (66048) | W_s 40*512 f (81920)   = 147968
//     MAIN:  buf 16384 u64 (131072) | cur 1024 u64 (8192)    = 139264
// ---------------------------------------------------------------------------
#define OFF_UNION  11072
#define TOT_SMEM   (OFF_UNION + 147968)

__global__ void __launch_bounds__(NTHR, 1)
quixer_kernel(const float* __restrict__ emb, const float* __restrict__ W,
              const float* __restrict__ bias,
              const float* __restrict__ lcu_re, const float* __restrict__ lcu_im,
              const float* __restrict__ qsvt, const float* __restrict__ ffp,
              float* __restrict__ out) {
    extern __shared__ char smraw[];
    float*  cs_s  = (float*)smraw;                       // 2560 f
    float*  ffcs  = cs_s + 2560;                         // 80 f
    float2* lcu_s = (float2*)(ffcs + 80);                // 32 f2
    float*  rsum  = (float*)(lcu_s + 32);                // 64 f
    char*   un    = smraw + OFF_UNION;
    float*  emb_s = (float*)un;                          // 32*516
    float*  W_s   = emb_s + 32 * 516;                    // 40*512
    u64*    buf   = (u64*)un;                            // 16*1024 u64
    u64*    cur   = buf + 16 * 1024;                     // 1024 u64

    const int b   = blockIdx.x;
    const int tid = threadIdx.x;
    const int w   = tid >> 5;
    const unsigned lane = tid & 31u;
    const int wb    = w & 1;
    const int pair  = w >> 1;
    const int grp   = w >> 2;                 // 4-warp group 0..7
    const int gt    = tid & (GRP - 1);        // id within group
    const int pgt   = gt ^ 32;                // partner within group
    const int barid = 1 + grp;                // named bars 1..8
    ulonglong2* Eg  = (ulonglong2*)buf + grp * 1024;  // 16KB slab per group
    float*      Fg  = (float*)Eg;

    // ---------------- phase 1: GEMM + trig (float4 paths) ----------------
    {
        const float4* embg   = (const float4*)(emb + (size_t)b * 32 * 512);
        float4*       emb_s4 = (float4*)emb_s;
        for (int i = tid; i < 4096; i += NTHR) {
            int l = i >> 7, d4 = i & 127;
            emb_s4[l * 129 + d4] = embg[i];
        }
        const float4* Wg   = (const float4*)W;
        float4*       W_s4 = (float4*)W_s;
        for (int i = tid; i < 5120; i += NTHR) W_s4[i] = Wg[i];
    }

    if (tid < 40) {
        float sv, cv;
        __sincosf(0.5f * ffp[tid], &sv, &cv);
        ffcs[2 * tid] = cv;
        ffcs[2 * tid + 1] = sv;
    }
    if (w == 1) {
        float re = lcu_re[lane], im = lcu_im[lane];
        float S = sqrtf(re * re + im * im);
#pragma unroll
        for (int m = 16; m; m >>= 1) S += __shfl_xor_sync(0xffffffffu, S, m);
        lcu_s[lane] = make_float2(re / S, im / S);
    }
    __syncthreads();

    if (tid < 256) {
        const int l  = tid & 31;
        const int kg = tid >> 5;             // 0..7, each handles 5 k's
        float acc5[5] = {0.f, 0.f, 0.f, 0.f, 0.f};
        const float4* er = (const float4*)emb_s + l * 129;
        const float4* wr = (const float4*)W_s + kg * 5 * 128;
#pragma unroll 2
        for (int d = 0; d < 128; ++d) {
            float4 a = er[d];
#pragma unroll
            for (int j = 0; j < 5; ++j) {
                float4 wv = wr[j * 128 + d];
                acc5[j] += a.x * wv.x + a.y * wv.y + a.z * wv.z + a.w * wv.w;
            }
        }
#pragma unroll
        for (int j = 0; j < 5; ++j) {
            int k = kg * 5 + j;
            float th = 0.5f * (acc5[j] + bias[k]);
            float sv, cv;
            __sincosf(th, &sv, &cv);
            cs_s[l * 80 + 2 * k]     = cv;
            cs_s[l * 80 + 2 * k + 1] = sv;
        }
    }
    __syncthreads();   // cs ready; union region free for buf/cur

    // ---------------- phase 2: QSVT mainloop ----------------
    const float q0 = qsvt[0], q1 = qsvt[1], q2 = qsvt[2];
    u64 acc = (tid == 0) ? F2(make_float2(q0, 0.f)) : 0ull;

    u64 X[8], Y[8];
    const int wbp = tid >> 9;
    const int r   = tid & 511;

    for (int step = 1; step <= 2; ++step) {
        const float qk = (step == 1) ? q1 : q2;
        u64 m = 0ull;
        for (int pass = 0; pass < 2; ++pass) {
            const int l = pair + pass * 16;
            const float* csl = cs_s + l * 80;
            if (step == 1) {
                build_ry_product(X, Y, csl, lane, wb);
                crx10_y0(X, Y, csl[20], csl[21], lane, Eg, gt, pgt, barid);
                run_gates<11>(X, Y, csl, lane, wb, Eg, Fg, gt, pgt, barid);
            } else {
#pragma unroll
                for (int v = 0; v < 8; ++v) {
                    X[v] = cur[wb * 512 + v * 32 + lane];
                    Y[v] = cur[wb * 512 + 256 + v * 32 + lane];
                }
                run_gates<0>(X, Y, csl, lane, wb, Eg, Fg, gt, pgt, barid);
            }
            // complex LCU scale
            const float2 lw = lcu_s[l];
            const u64 av = F2(make_float2(lw.x, lw.x));
            const u64 bp = F2(make_float2(lw.y, lw.y));
            const u64 bn = F2(make_float2(-lw.y, -lw.y));
#pragma unroll
            for (int v = 0; v < 8; ++v) {
                u64 tx = X[v];
                X[v] = fma2(bn, Y[v], mul2(av, tx));
                Y[v] = fma2(bp, tx, mul2(av, Y[v]));
            }
            // stage to buf (own slab region; ordered vs group by last gate pairbar)
            u64* rw = buf + w * 512;
#pragma unroll
            for (int v = 0; v < 8; ++v) {
                rw[v * 32 + lane]       = X[v];
                rw[256 + v * 32 + lane] = Y[v];
            }
            __syncthreads();
            // flat 16-way sum over pairs; 2 accumulators for ILP
            u64 a0 = buf[wbp * 512 + r];
            u64 a1 = buf[(2 + wbp) * 512 + r];
#pragma unroll
            for (int p = 2; p < 16; p += 2) {
                a0 = add2(a0, buf[(2 * p + wbp) * 512 + r]);
                a1 = add2(a1, buf[(2 * p + 2 + wbp) * 512 + r]);
            }
            u64 a = add2(a0, a1);
            m = (pass == 0) ? a : add2(m, a);
            __syncthreads();                 // before next pass reuses buf
        }
        const u64 qk2 = F2(make_float2(qk, qk));
        acc = fma2(qk2, m, acc);
        if (step == 1) {
            cur[tid] = m;
            __syncthreads();
        }
    }

    // normalize acc
    {
        float2 t0 = U2(acc);
        float p = t0.x * t0.x + t0.y * t0.y;
#pragma unroll
        for (int mm = 16; mm; mm >>= 1) p += __shfl_xor_sync(0xffffffffu, p, mm);
        if (lane == 0) rsum[w] = p;
    }
    __syncthreads();
    if (tid == 0) {
        float t = 0.f;
#pragma unroll
        for (int i = 0; i < 32; ++i) t += rsum[i];
        rsum[0] = rsqrtf(t);
    }
    __syncthreads();
    {
        const float inv = rsum[0];
        cur[tid] = mul2(acc, F2(make_float2(inv, inv)));
    }
    __syncthreads();

    // feed-forward PQC: ALL pairs compute redundantly (identical params)
#pragma unroll
    for (int v = 0; v < 8; ++v) {
        X[v] = cur[wb * 512 + v * 32 + lane];
        Y[v] = cur[wb * 512 + 256 + v * 32 + lane];
    }
    run_gates<0>(X, Y, ffcs, lane, wb, Eg, Fg, gt, pgt, barid);

    // measurement: pair p (warps 2p, 2p+1) measures wire p from registers.
    if (w < 20) {
        u64 cr2 = 0ull, ci2 = 0ull, zz2 = 0ull;
        float cr = 0.f, ci = 0.f, zz = 0.f;

        // wire 0 (P=9): warp wb=1 of pair 0 stages its half into group-0 slab
        if (pair == 0 && wb == 1) {
            u64* S = (u64*)Eg;
#pragma unroll
            for (int v = 0; v < 8; ++v) {
                S[v * 32 + lane]       = X[v];
                S[(8 + v) * 32 + lane] = Y[v];
            }
        }
        if (grp == 0) pairbar(1);     // all 4 warps of group 0 participate

        switch (pair) {
            case 0:
                if (wb == 0) {
                    const u64* S = (const u64*)Eg;
                    const u64 M1 = F2(make_float2(-1.f, -1.f));
#pragma unroll
                    for (int v = 0; v < 8; ++v) {
                        u64 X1 = S[v * 32 + lane];
                        u64 Y1 = S[(8 + v) * 32 + lane];
                        cr2 = add2(cr2, fma2(Y[v], Y1, mul2(X[v], X1)));
                        ci2 = add2(ci2, fma2(X[v], Y1, mul2(mul2(Y[v], X1), M1)));
                        u64 n0 = fma2(Y[v], Y[v], mul2(X[v], X[v]));
                        u64 n1 = fma2(Y1, Y1, mul2(X1, X1));
                        zz2 = add2(zz2, add2(n0, mul2(n1, M1)));
                    }
                }
                break;
            case 1: meas_pack(X, Y, cr, ci, zz); break;
            case 2: meas_vbit<2>(X, Y, cr2, ci2, zz2); break;   // P=7
            case 3: meas_vbit<1>(X, Y, cr2, ci2, zz2); break;   // P=6
            case 4: meas_vbit<0>(X, Y, cr2, ci2, zz2); break;   // P=5
            case 5: meas_lane<4>(X, Y, lane, cr2, ci2, zz2); break;
            case 6: meas_lane<3>(X, Y, lane, cr2, ci2, zz2); break;
            case 7: meas_lane<2>(X, Y, lane, cr2, ci2, zz2); break;
            case 8: meas_lane<1>(X, Y, lane, cr2, ci2, zz2); break;
            case 9: meas_lane<0>(X, Y, lane, cr2, ci2, zz2); break;
        }
        // fold packed accumulators
        {
            float2 a = U2(cr2); cr += a.x + a.y;
            float2 bb = U2(ci2); ci += bb.x + bb.y;
            float2 cc = U2(zz2); zz += cc.x + cc.y;
        }
#pragma unroll
        for (int mm = 16; mm; mm >>= 1) {
            cr += __shfl_xor_sync(0xffffffffu, cr, mm);
            ci += __shfl_xor_sync(0xffffffffu, ci, mm);
            zz += __shfl_xor_sync(0xffffffffu, zz, mm);
        }
        if (lane == 0) {
            rsum[w * 3 + 0] = cr;
            rsum[w * 3 + 1] = ci;
            rsum[w * 3 + 2] = zz;
        }
        pairbar(barid);               // groups 0..4; all member warps measuring
        if (wb == 0 && lane == 0) {
            float crt = rsum[w * 3 + 0] + rsum[(w + 1) * 3 + 0];
            float cit = rsum[w * 3 + 1] + rsum[(w + 1) * 3 + 1];
            float zzt = rsum[w * 3 + 2] + rsum[(w + 1) * 3 + 2];
            float* outb = out + b * 30;
            outb[pair]      = 2.0f * crt;
            outb[10 + pair] = 2.0f * cit;
            outb[20 + pair] = zzt;
        }
    }
}

// ---------------------------------------------------------------------------
extern "C" void kernel_launch(void* const* d_in, const int* in_sizes, int n_in,
                              void* d_out, int out_size) {
    const float* emb    = (const float*)d_in[0];
    const float* W      = (const float*)d_in[1];
    const float* bias   = (const float*)d_in[2];
    const float* lcu_re = (const float*)d_in[3];
    const float* lcu_im = (const float*)d_in[4];
    const float* qsvt   = (const float*)d_in[5];
    const float* ffp    = (const float*)d_in[6];
    float* out = (float*)d_out;

    cudaFuncSetAttribute(quixer_kernel, cudaFuncAttributeMaxDynamicSharedMemorySize, TOT_SMEM);
    quixer_kernel<<<NB, NTHR, TOT_SMEM>>>(emb, W, bias, lcu_re, lcu_im, qsvt, ffp, out);
}

// round 12
// speedup vs baseline: 1.0634x; 1.0634x over previous
#include <cuda_runtime.h>
#include <math.h>

#define NL     32
#define NB     128
#define NPQ    40
#define NTHR   1024
#define GRP    128      // threads per barrier group (4 warps)

typedef unsigned long long u64;

// ---------------------------------------------------------------------------
// gate tables.  bit position = 9 - wire.
// type: 0 = RY (PA = bit pos), 1 = CRX (PA = control bit, PB = target bit)
// RY gates are stored in TANGENT form: cs[2k] = tan(theta/2); the scalar
// prod(cos) over all 20 RY gates of a circuit is folded into the LCU weight
// (mainloop) or the normalization scalar (ff circuit).
// CRX gates keep (cos, sin) in cs[2k], cs[2k+1].
// ---------------------------------------------------------------------------
constexpr int G_TYPE[40] = {0,0,0,0,0,0,0,0,0,0, 1,1,1,1,1,1,1,1,1,1,
                            0,0,0,0,0,0,0,0,0,0, 1,1,1,1,1,1,1,1,1,1};
constexpr int G_PA[40]   = {9,8,7,6,5,4,3,2,1,0, 0,1,2,3,4,5,6,7,8,9,
                            9,8,7,6,5,4,3,2,1,0, 0,9,8,7,6,5,4,3,2,1};
constexpr int G_PB[40]   = {0,0,0,0,0,0,0,0,0,0, 9,0,1,2,3,4,5,6,7,8,
                            0,0,0,0,0,0,0,0,0,0, 1,0,9,8,7,6,5,4,3,2};

// ---------------------------------------------------------------------------
// f32x2 helpers
// ---------------------------------------------------------------------------
__device__ __forceinline__ u64 F2(float2 v) {
    u64 r; asm("mov.b64 %0, {%1,%2};" : "=l"(r) : "f"(v.x), "f"(v.y)); return r;
}
__device__ __forceinline__ float2 U2(u64 v) {
    float2 p; asm("mov.b64 {%0,%1}, %2;" : "=f"(p.x), "=f"(p.y) : "l"(v)); return p;
}
__device__ __forceinline__ u64 fma2(u64 a, u64 b, u64 c) {
    u64 d; asm("fma.rn.f32x2 %0, %1, %2, %3;" : "=l"(d) : "l"(a), "l"(b), "l"(c)); return d;
}
__device__ __forceinline__ u64 mul2(u64 a, u64 b) {
    u64 d; asm("mul.rn.f32x2 %0, %1, %2;" : "=l"(d) : "l"(a), "l"(b)); return d;
}
__device__ __forceinline__ u64 add2(u64 a, u64 b) {
    u64 d; asm("add.rn.f32x2 %0, %1, %2;" : "=l"(d) : "l"(a), "l"(b)); return d;
}
template<int M>
__device__ __forceinline__ u64 shfl2(u64 v) {
    float2 t = U2(v);
    t.x = __shfl_xor_sync(0xffffffffu, t.x, M);
    t.y = __shfl_xor_sync(0xffffffffu, t.y, M);
    return F2(t);
}
__device__ __forceinline__ u64 swap2(u64 v) {
    float2 t = U2(v);
    return F2(make_float2(t.y, t.x));
}
__device__ __forceinline__ void pairbar(int id) {
    asm volatile("bar.sync %0, 128;" :: "r"(id) : "memory");
}

// ---------------------------------------------------------------------------
// state: each PAIR of warps (w, w^1) holds one 1024-amp state.
//   amp = (wb<<9) | (pack<<8) | (v<<5) | lane ;  warp holds X[8], Y[8] u64
//   P<5 -> lane (shfl); 5<=P<8 -> v bit; P==8 -> pack (swap2); P==9 -> warp bit
// ---------------------------------------------------------------------------

// ---- RY gates, tangent form: out = in + (+-t) * partner (scale folded out) ----
template<int P>
__device__ __forceinline__ void ry_lane_t(u64 (&X)[8], u64 (&Y)[8], float t, unsigned lane) {
    const float sg = ((lane >> P) & 1u) ? t : -t;
    const u64 sg2 = F2(make_float2(sg, sg));
#pragma unroll
    for (int v = 0; v < 8; ++v) {
        X[v] = fma2(sg2, shfl2<(1 << P)>(X[v]), X[v]);
        Y[v] = fma2(sg2, shfl2<(1 << P)>(Y[v]), Y[v]);
    }
}
template<int RB>
__device__ __forceinline__ void ry_reg_t(u64 (&X)[8], u64 (&Y)[8], float t) {
    const u64 tp = F2(make_float2(t, t)), tn = F2(make_float2(-t, -t));
#pragma unroll
    for (int v0 = 0; v0 < 8; ++v0) {
        if (v0 & (1 << RB)) continue;
        const int v1 = v0 | (1 << RB);
        u64 ax0 = X[v0], ay0 = Y[v0];
        X[v0] = fma2(tn, X[v1], ax0);
        X[v1] = fma2(tp, ax0, X[v1]);
        Y[v0] = fma2(tn, Y[v1], ay0);
        Y[v1] = fma2(tp, ay0, Y[v1]);
    }
}
__device__ __forceinline__ void ry_pack_t(u64 (&X)[8], u64 (&Y)[8], float t) {
    const u64 tv = F2(make_float2(-t, t));
#pragma unroll
    for (int v = 0; v < 8; ++v) {
        X[v] = fma2(tv, swap2(X[v]), X[v]);
        Y[v] = fma2(tv, swap2(Y[v]), Y[v]);
    }
}
// RY on warp bit (tangent): smem exchange then single fma
__device__ __forceinline__ void ry_warp_t(u64 (&X)[8], u64 (&Y)[8], float t,
                                          ulonglong2* Eg, int gt, int pgt, int barid, int wb) {
#pragma unroll
    for (int i = 0; i < 4; ++i)
        Eg[i * GRP + gt] = make_ulonglong2(X[2 * i], X[2 * i + 1]);
#pragma unroll
    for (int i = 0; i < 4; ++i)
        Eg[(4 + i) * GRP + gt] = make_ulonglong2(Y[2 * i], Y[2 * i + 1]);
    pairbar(barid);
    const float sg = wb ? t : -t;
    const u64 sg2 = F2(make_float2(sg, sg));
#pragma unroll
    for (int i = 0; i < 4; ++i) {
        ulonglong2 p = Eg[i * GRP + pgt];
        X[2 * i]     = fma2(sg2, p.x, X[2 * i]);
        X[2 * i + 1] = fma2(sg2, p.y, X[2 * i + 1]);
    }
#pragma unroll
    for (int i = 0; i < 4; ++i) {
        ulonglong2 p = Eg[(4 + i) * GRP + pgt];
        Y[2 * i]     = fma2(sg2, p.x, Y[2 * i]);
        Y[2 * i + 1] = fma2(sg2, p.y, Y[2 * i + 1]);
    }
    pairbar(barid);
}
// CRX k=10: control = lane bit 0, target = warp bit.  Only odd lanes exchange.
__device__ __forceinline__ void crx10(u64 (&X)[8], u64 (&Y)[8], float c, float s,
                                      unsigned lane, ulonglong2* Eg, int gt, int pgt, int barid) {
    const bool act = (lane & 1u) != 0u;
    if (act) {
#pragma unroll
        for (int i = 0; i < 4; ++i)
            Eg[i * GRP + gt] = make_ulonglong2(X[2 * i], X[2 * i + 1]);
#pragma unroll
        for (int i = 0; i < 4; ++i)
            Eg[(4 + i) * GRP + gt] = make_ulonglong2(Y[2 * i], Y[2 * i + 1]);
    }
    pairbar(barid);
    if (act) {
        const u64 cc = F2(make_float2(c, c));
        const u64 sp = F2(make_float2(s, s)), sn = F2(make_float2(-s, -s));
#pragma unroll
        for (int i = 0; i < 4; ++i) {
            ulonglong2 py = Eg[(4 + i) * GRP + pgt];
            X[2 * i]     = fma2(sp, py.x, mul2(cc, X[2 * i]));
            X[2 * i + 1] = fma2(sp, py.y, mul2(cc, X[2 * i + 1]));
        }
#pragma unroll
        for (int i = 0; i < 4; ++i) {
            ulonglong2 px = Eg[i * GRP + pgt];
            Y[2 * i]     = fma2(sn, px.x, mul2(cc, Y[2 * i]));
            Y[2 * i + 1] = fma2(sn, px.y, mul2(cc, Y[2 * i + 1]));
        }
    }
    pairbar(barid);
}
// CRX k=10 with Y==0 everywhere (step-1 fast path): exchange X only.
__device__ __forceinline__ void crx10_y0(u64 (&X)[8], u64 (&Y)[8], float c, float s,
                                         unsigned lane, ulonglong2* Eg, int gt, int pgt, int barid) {
    const bool act = (lane & 1u) != 0u;
    if (act) {
#pragma unroll
        for (int i = 0; i < 4; ++i)
            Eg[i * GRP + gt] = make_ulonglong2(X[2 * i], X[2 * i + 1]);
    }
    pairbar(barid);
    if (act) {
        const u64 cc = F2(make_float2(c, c));
        const u64 sn = F2(make_float2(-s, -s));
#pragma unroll
        for (int i = 0; i < 4; ++i) {
            ulonglong2 px = Eg[i * GRP + pgt];
            Y[2 * i]     = mul2(sn, px.x);
            Y[2 * i + 1] = mul2(sn, px.y);
            X[2 * i]     = mul2(cc, X[2 * i]);
            X[2 * i + 1] = mul2(cc, X[2 * i + 1]);
        }
    }
    pairbar(barid);
}
// CRX k=32: control = pack bit (hi half), target = warp bit.  Exchange hi floats only.
__device__ __forceinline__ void crx32(u64 (&X)[8], u64 (&Y)[8], float c, float s,
                                      float* Fg, int gt, int pgt, int barid) {
#pragma unroll
    for (int i = 0; i < 8; ++i) Fg[i * GRP + gt] = U2(X[i]).y;
#pragma unroll
    for (int i = 0; i < 8; ++i) Fg[(8 + i) * GRP + gt] = U2(Y[i]).y;
    pairbar(barid);
#pragma unroll
    for (int i = 0; i < 8; ++i) {
        float pxh = Fg[i * GRP + pgt];
        float pyh = Fg[(8 + i) * GRP + pgt];
        float2 x = U2(X[i]), y = U2(Y[i]);
        x.y = fmaf(s, pyh, c * x.y);
        y.y = fmaf(-s, pxh, c * y.y);
        X[i] = F2(x); Y[i] = F2(y);
    }
    pairbar(barid);
}

// RX (warp-bit-controlled, executes locally on wb==1) on target B != 9
template<int B>
__device__ __forceinline__ void rx_local(u64 (&X)[8], u64 (&Y)[8], float c, float s) {
    const u64 ce2 = F2(make_float2(c, c));
    const u64 se2 = F2(make_float2(s, s)), sn2 = F2(make_float2(-s, -s));
    if constexpr (B < 5) {
#pragma unroll
        for (int v = 0; v < 8; ++v) {
            u64 px = shfl2<(1 << B)>(X[v]);
            u64 py = shfl2<(1 << B)>(Y[v]);
            X[v] = fma2(se2, py, mul2(ce2, X[v]));
            Y[v] = fma2(sn2, px, mul2(ce2, Y[v]));
        }
    } else if constexpr (B < 8) {
        constexpr int TB = 1 << (B - 5);
#pragma unroll
        for (int v0 = 0; v0 < 8; ++v0) {
            if (v0 & TB) continue;
            const int v1 = v0 | TB;
            u64 a0x = X[v0], a0y = Y[v0], a1x = X[v1], a1y = Y[v1];
            X[v0] = fma2(se2, a1y, mul2(ce2, a0x));
            Y[v0] = fma2(sn2, a1x, mul2(ce2, a0y));
            X[v1] = fma2(se2, a0y, mul2(ce2, a1x));
            Y[v1] = fma2(sn2, a0x, mul2(ce2, a1y));
        }
    } else {
#pragma unroll
        for (int v = 0; v < 8; ++v) {
            u64 sx = swap2(X[v]), sy = swap2(Y[v]);
            X[v] = fma2(se2, sy, mul2(ce2, X[v]));
            Y[v] = fma2(sn2, sx, mul2(ce2, Y[v]));
        }
    }
}

// CRX, control A != 9, target B != 9
template<int A, int B>
__device__ __forceinline__ void crx_gate(u64 (&X)[8], u64 (&Y)[8], float c, float s, unsigned lane) {
    float2 cef, sef;
    if constexpr (A < 5) {
        const int cb = (lane >> A) & 1u;
        const float ce = cb ? c : 1.0f, se = cb ? s : 0.0f;
        cef = make_float2(ce, ce); sef = make_float2(se, se);
    } else if constexpr (A == 8) {
        cef = make_float2(1.0f, c); sef = make_float2(0.0f, s);
    } else {
        cef = make_float2(c, c); sef = make_float2(s, s);
    }
    const u64 ce2 = F2(cef), se2 = F2(sef), sn2 = F2(make_float2(-sef.x, -sef.y));
    constexpr bool vctrl = (A >= 5 && A < 8);
    constexpr int CB = vctrl ? (1 << (A - 5)) : 0;

    if constexpr (B < 5) {
#pragma unroll
        for (int v = 0; v < 8; ++v) {
            if (vctrl && !(v & CB)) continue;
            u64 px = shfl2<(1 << B)>(X[v]);
            u64 py = shfl2<(1 << B)>(Y[v]);
            X[v] = fma2(se2, py, mul2(ce2, X[v]));
            Y[v] = fma2(sn2, px, mul2(ce2, Y[v]));
        }
    } else if constexpr (B < 8) {
        constexpr int TB = 1 << (B - 5);
#pragma unroll
        for (int v0 = 0; v0 < 8; ++v0) {
            if (v0 & TB) continue;
            if (vctrl && !(v0 & CB)) continue;
            const int v1 = v0 | TB;
            u64 a0x = X[v0], a0y = Y[v0], a1x = X[v1], a1y = Y[v1];
            X[v0] = fma2(se2, a1y, mul2(ce2, a0x));
            Y[v0] = fma2(sn2, a1x, mul2(ce2, a0y));
            X[v1] = fma2(se2, a0y, mul2(ce2, a1x));
            Y[v1] = fma2(sn2, a0x, mul2(ce2, a1y));
        }
    } else {
#pragma unroll
        for (int v = 0; v < 8; ++v) {
            if (vctrl && !(v & CB)) continue;
            u64 sx = swap2(X[v]), sy = swap2(Y[v]);
            X[v] = fma2(se2, sy, mul2(ce2, X[v]));
            Y[v] = fma2(sn2, sx, mul2(ce2, Y[v]));
        }
    }
}

template<int K>
__device__ __forceinline__ void do_gate(u64 (&X)[8], u64 (&Y)[8], const float* csl,
                                        unsigned lane, int wb,
                                        ulonglong2* Eg, float* Fg, int gt, int pgt, int barid) {
    const float c = csl[2 * K];          // t for RY gates, cos for CRX gates
    const float s = csl[2 * K + 1];      // (c for RY, unused) / sin for CRX
    constexpr int A = G_PA[K], Bp = G_PB[K];
    if constexpr (K == 0 || K == 20) {
        ry_warp_t(X, Y, c, Eg, gt, pgt, barid, wb);
    } else if constexpr (K == 10) {
        crx10(X, Y, c, s, lane, Eg, gt, pgt, barid);
    } else if constexpr (K == 32) {
        crx32(X, Y, c, s, Fg, gt, pgt, barid);
    } else if constexpr (G_TYPE[K] == 1 && A == 9) {
        if (wb) rx_local<Bp>(X, Y, c, s);
    } else if constexpr (G_TYPE[K] == 0) {
        if constexpr (A == 8)      ry_pack_t(X, Y, c);
        else if constexpr (A >= 5) ry_reg_t<A - 5>(X, Y, c);
        else                       ry_lane_t<A>(X, Y, c, lane);
    } else {
        crx_gate<A, Bp>(X, Y, c, s, lane);
    }
}

template<int K, int KEND = 40>
__device__ __forceinline__ void run_gates(u64 (&X)[8], u64 (&Y)[8], const float* csl,
                                          unsigned lane, int wb,
                                          ulonglong2* Eg, float* Fg, int gt, int pgt, int barid) {
    if constexpr (K < KEND) {
        do_gate<K>(X, Y, csl, lane, wb, Eg, Fg, gt, pgt, barid);
        run_gates<K + 1, KEND>(X, Y, csl, lane, wb, Eg, Fg, gt, pgt, barid);
    }
}

// ---- step-1 shortcut: product state after first RY layer, tangent form ----
// unscaled amp(idx) = prod over bits (bit ? t_k : 1); the prod(cos) is in lcu.
__device__ __forceinline__ void build_ry_product(u64 (&X)[8], u64 (&Y)[8],
                                                 const float* cs, unsigned lane, int wb) {
    float A = wb ? cs[0] : 1.0f;                       // P=9, k=0
    A *= (lane & 1u)  ? cs[18] : 1.0f;                 // P=0, k=9
    A *= (lane & 2u)  ? cs[16] : 1.0f;                 // P=1, k=8
    A *= (lane & 4u)  ? cs[14] : 1.0f;                 // P=2, k=7
    A *= (lane & 8u)  ? cs[12] : 1.0f;                 // P=3, k=6
    A *= (lane & 16u) ? cs[10] : 1.0f;                 // P=4, k=5
    const float t4 = cs[8], t3 = cs[6], t2 = cs[4], t1 = cs[2];
    float fv[8];
    fv[0] = 1.f;     fv[1] = t4;      fv[2] = t3;      fv[3] = t4 * t3;
    fv[4] = t2;      fv[5] = t4 * t2; fv[6] = t3 * t2; fv[7] = t4 * t3 * t2;
#pragma unroll
    for (int v = 0; v < 8; ++v) {
        const float g = A * fv[v];
        X[v] = F2(make_float2(g, g * t1));
        Y[v] = 0ull;
    }
}

// ---- register-resident measurement helpers (wire = pair, P = 9-pair) ----
template<int P>
__device__ __forceinline__ void meas_lane(const u64 (&X)[8], const u64 (&Y)[8], unsigned lane,
                                          u64& cr2, u64& ci2, u64& zz2) {
    const int bit = (lane >> P) & 1u;
    const u64 f02 = F2(bit ? make_float2(0.f, 0.f) : make_float2(1.f, 1.f));
    const u64 zs2 = F2(bit ? make_float2(-1.f, -1.f) : make_float2(1.f, 1.f));
    const u64 M1  = F2(make_float2(-1.f, -1.f));
#pragma unroll
    for (int v = 0; v < 8; ++v) {
        u64 px = shfl2<(1 << P)>(X[v]);
        u64 py = shfl2<(1 << P)>(Y[v]);
        u64 t1 = fma2(Y[v], py, mul2(X[v], px));
        cr2 = fma2(f02, t1, cr2);
        u64 t2 = fma2(X[v], py, mul2(mul2(Y[v], px), M1));
        ci2 = fma2(f02, t2, ci2);
        u64 nn = fma2(Y[v], Y[v], mul2(X[v], X[v]));
        zz2 = fma2(zs2, nn, zz2);
    }
}
template<int RB>
__device__ __forceinline__ void meas_vbit(const u64 (&X)[8], const u64 (&Y)[8],
                                          u64& cr2, u64& ci2, u64& zz2) {
    const u64 M1 = F2(make_float2(-1.f, -1.f));
#pragma unroll
    for (int v0 = 0; v0 < 8; ++v0) {
        if (v0 & (1 << RB)) continue;
        const int v1 = v0 | (1 << RB);
        cr2 = add2(cr2, fma2(Y[v0], Y[v1], mul2(X[v0], X[v1])));
        ci2 = add2(ci2, fma2(X[v0], Y[v1], mul2(mul2(Y[v0], X[v1]), M1)));
        u64 n0 = fma2(Y[v0], Y[v0], mul2(X[v0], X[v0]));
        u64 n1 = fma2(Y[v1], Y[v1], mul2(X[v1], X[v1]));
        zz2 = add2(zz2, add2(n0, mul2(n1, M1)));
    }
}
__device__ __forceinline__ void meas_pack(const u64 (&X)[8], const u64 (&Y)[8],
                                          float& cr, float& ci, float& zz) {
#pragma unroll
    for (int v = 0; v < 8; ++v) {
        float2 x = U2(X[v]), y = U2(Y[v]);
        cr += x.x * x.y + y.x * y.y;
        ci += x.x * y.y - y.x * x.y;
        zz += (x.x * x.x + y.x * y.x) - (x.y * x.y + y.y * y.y);
    }
}

// ---------------------------------------------------------------------------
// smem layout (bytes):
//   [0,10240)      cs_s   2560 f
//   [10240,10560)  ffcs   80 f
//   [10560,10816)  lcu_s  32 f2
//   [10816,11072)  rsum   64 f
//   [11072,11584)  cscale 128 f
//   [11584,11600)  sff    4 f (1 used)
//   [11600, ...)   UNION:
//     GEMM:  emb_s 32*516 f (66048) | W_s 40*512 f (81920)   = 147968
//     MAIN:  buf 16384 u64 (131072) | cur 1024 u64 (8192)    = 139264
// ---------------------------------------------------------------------------
#define OFF_UNION  11600
#define TOT_SMEM   (OFF_UNION + 147968)

__global__ void __launch_bounds__(NTHR, 1)
quixer_kernel(const float* __restrict__ emb, const float* __restrict__ W,
              const float* __restrict__ bias,
              const float* __restrict__ lcu_re, const float* __restrict__ lcu_im,
              const float* __restrict__ qsvt, const float* __restrict__ ffp,
              float* __restrict__ out) {
    extern __shared__ char smraw[];
    float*  cs_s   = (float*)smraw;                      // 2560 f
    float*  ffcs   = cs_s + 2560;                        // 80 f
    float2* lcu_s  = (float2*)(ffcs + 80);               // 32 f2
    float*  rsum   = (float*)(lcu_s + 32);               // 64 f
    float*  cscale = rsum + 64;                          // 128 f
    float*  sff    = cscale + 128;                       // 1 f
    char*   un     = smraw + OFF_UNION;
    float*  emb_s  = (float*)un;                         // 32*516
    float*  W_s    = emb_s + 32 * 516;                   // 40*512
    u64*    buf    = (u64*)un;                           // 16*1024 u64
    u64*    cur    = buf + 16 * 1024;                    // 1024 u64

    const int b   = blockIdx.x;
    const int tid = threadIdx.x;
    const int w   = tid >> 5;
    const unsigned lane = tid & 31u;
    const int wb    = w & 1;
    const int pair  = w >> 1;
    const int grp   = w >> 2;
    const int gt    = tid & (GRP - 1);
    const int pgt   = gt ^ 32;
    const int barid = 1 + grp;
    ulonglong2* Eg  = (ulonglong2*)buf + grp * 1024;
    float*      Fg  = (float*)Eg;

    // ---------------- phase 1: GEMM + trig (float4 paths) ----------------
    {
        const float4* embg   = (const float4*)(emb + (size_t)b * 32 * 512);
        float4*       emb_s4 = (float4*)emb_s;
        for (int i = tid; i < 4096; i += NTHR) {
            int l = i >> 7, d4 = i & 127;
            emb_s4[l * 129 + d4] = embg[i];
        }
        const float4* Wg   = (const float4*)W;
        float4*       W_s4 = (float4*)W_s;
        for (int i = tid; i < 5120; i += NTHR) W_s4[i] = Wg[i];
    }

    if (tid < 40) {
        float sv, cv;
        __sincosf(0.5f * ffp[tid], &sv, &cv);
        const bool isRY = (tid < 10) || (tid >= 20 && tid < 30);
        if (isRY) {
            ffcs[2 * tid]     = __fdividef(sv, cv);      // tangent
            ffcs[2 * tid + 1] = cv;                      // cos (for the product)
        } else {
            ffcs[2 * tid]     = cv;
            ffcs[2 * tid + 1] = sv;
        }
    }
    if (w == 1) {
        float re = lcu_re[lane], im = lcu_im[lane];
        float S = sqrtf(re * re + im * im);
#pragma unroll
        for (int m = 16; m; m >>= 1) S += __shfl_xor_sync(0xffffffffu, S, m);
        lcu_s[lane] = make_float2(re / S, im / S);
    }
    __syncthreads();

    if (tid < 256) {
        const int l  = tid & 31;
        const int kg = tid >> 5;             // 0..7, each handles 5 k's
        float acc5[5] = {0.f, 0.f, 0.f, 0.f, 0.f};
        const float4* er = (const float4*)emb_s + l * 129;
        const float4* wr = (const float4*)W_s + kg * 5 * 128;
#pragma unroll 2
        for (int d = 0; d < 128; ++d) {
            float4 a = er[d];
#pragma unroll
            for (int j = 0; j < 5; ++j) {
                float4 wv = wr[j * 128 + d];
                acc5[j] += a.x * wv.x + a.y * wv.y + a.z * wv.z + a.w * wv.w;
            }
        }
        const bool ryGroup = (kg == 0) || (kg == 1) || (kg == 4) || (kg == 5);
        float p5 = 1.0f;
#pragma unroll
        for (int j = 0; j < 5; ++j) {
            int k = kg * 5 + j;
            float th = 0.5f * (acc5[j] + bias[k]);
            float sv, cv;
            __sincosf(th, &sv, &cv);
            if (ryGroup) {
                cs_s[l * 80 + 2 * k]     = __fdividef(sv, cv);  // tangent
                cs_s[l * 80 + 2 * k + 1] = cv;
                p5 *= cv;
            } else {
                cs_s[l * 80 + 2 * k]     = cv;
                cs_s[l * 80 + 2 * k + 1] = sv;
            }
        }
        if (ryGroup) {
            const int idx = (kg < 2) ? kg : kg - 2;     // 0,1,2,3
            cscale[l * 4 + idx] = p5;
        }
    }
    __syncthreads();

    // fold prod(cos) into lcu weights; compute ff scale
    if (tid < 32) {
        float S = cscale[tid * 4] * cscale[tid * 4 + 1] *
                  cscale[tid * 4 + 2] * cscale[tid * 4 + 3];
        float2 lw = lcu_s[tid];
        lcu_s[tid] = make_float2(lw.x * S, lw.y * S);
    }
    if (tid == 33) {
        float S = 1.0f;
#pragma unroll
        for (int k = 0; k < 10; ++k)  S *= ffcs[2 * k + 1];
#pragma unroll
        for (int k = 20; k < 30; ++k) S *= ffcs[2 * k + 1];
        sff[0] = S;
    }
    __syncthreads();   // cs/lcu/sff ready; union region free for buf/cur

    // ---------------- phase 2: QSVT mainloop ----------------
    const float q0 = qsvt[0], q1 = qsvt[1], q2 = qsvt[2];
    u64 acc = (tid == 0) ? F2(make_float2(q0, 0.f)) : 0ull;

    u64 X[8], Y[8];
    const int wbp = tid >> 9;
    const int r   = tid & 511;

    for (int step = 1; step <= 2; ++step) {
        const float qk = (step == 1) ? q1 : q2;
        u64 m = 0ull;
        for (int pass = 0; pass < 2; ++pass) {
            const int l = pair + pass * 16;
            const float* csl = cs_s + l * 80;
            if (step == 1) {
                build_ry_product(X, Y, csl, lane, wb);
                crx10_y0(X, Y, csl[20], csl[21], lane, Eg, gt, pgt, barid);
                run_gates<11>(X, Y, csl, lane, wb, Eg, Fg, gt, pgt, barid);
            } else {
#pragma unroll
                for (int v = 0; v < 8; ++v) {
                    X[v] = cur[wb * 512 + v * 32 + lane];
                    Y[v] = cur[wb * 512 + 256 + v * 32 + lane];
                }
                run_gates<0>(X, Y, csl, lane, wb, Eg, Fg, gt, pgt, barid);
            }
            // complex LCU scale (includes folded prod-cos)
            const float2 lw = lcu_s[l];
            const u64 av = F2(make_float2(lw.x, lw.x));
            const u64 bp = F2(make_float2(lw.y, lw.y));
            const u64 bn = F2(make_float2(-lw.y, -lw.y));
#pragma unroll
            for (int v = 0; v < 8; ++v) {
                u64 tx = X[v];
                X[v] = fma2(bn, Y[v], mul2(av, tx));
                Y[v] = fma2(bp, tx, mul2(av, Y[v]));
            }
            // stage to buf (own region; ordered within group by last exchange bar)
            u64* rw = buf + w * 512;
#pragma unroll
            for (int v = 0; v < 8; ++v) {
                rw[v * 32 + lane]       = X[v];
                rw[256 + v * 32 + lane] = Y[v];
            }
            __syncthreads();
            // flat 16-way sum over pairs
            u64 a0 = buf[wbp * 512 + r];
            u64 a1 = buf[(2 + wbp) * 512 + r];
#pragma unroll
            for (int p = 2; p < 16; p += 2) {
                a0 = add2(a0, buf[(2 * p + wbp) * 512 + r]);
                a1 = add2(a1, buf[(2 * p + 2 + wbp) * 512 + r]);
            }
            u64 a = add2(a0, a1);
            m = (pass == 0) ? a : add2(m, a);
            if (pass == 0) __syncthreads();  // buf reused by next pass's exchanges
        }
        const u64 qk2 = F2(make_float2(qk, qk));
        acc = fma2(qk2, m, acc);
        if (step == 1) {
            cur[tid] = m;                    // cur disjoint from buf
            __syncthreads();                 // covers buf-free + cur-visible
        }
    }

    // normalize acc (last-pass buf readers ordered by the sync below)
    {
        float2 t0 = U2(acc);
        float p = t0.x * t0.x + t0.y * t0.y;
#pragma unroll
        for (int mm = 16; mm; mm >>= 1) p += __shfl_xor_sync(0xffffffffu, p, mm);
        if (lane == 0) rsum[w] = p;
    }
    __syncthreads();
    if (tid == 0) {
        float t = 0.f;
#pragma unroll
        for (int i = 0; i < 32; ++i) t += rsum[i];
        rsum[0] = rsqrtf(t) * sff[0];        // fold ff prod-cos into normalization
    }
    __syncthreads();
    {
        const float inv = rsum[0];
        cur[tid] = mul2(acc, F2(make_float2(inv, inv)));
    }
    __syncthreads();

    // feed-forward PQC: ALL pairs compute redundantly (identical params)
#pragma unroll
    for (int v = 0; v < 8; ++v) {
        X[v] = cur[wb * 512 + v * 32 + lane];
        Y[v] = cur[wb * 512 + 256 + v * 32 + lane];
    }
    run_gates<0>(X, Y, ffcs, lane, wb, Eg, Fg, gt, pgt, barid);

    // measurement: pair p measures wire p from registers
    if (w < 20) {
        u64 cr2 = 0ull, ci2 = 0ull, zz2 = 0ull;
        float cr = 0.f, ci = 0.f, zz = 0.f;

        if (pair == 0 && wb == 1) {
            u64* S = (u64*)Eg;
#pragma unroll
            for (int v = 0; v < 8; ++v) {
                S[v * 32 + lane]       = X[v];
                S[(8 + v) * 32 + lane] = Y[v];
            }
        }
        if (grp == 0) pairbar(1);

        switch (pair) {
            case 0:
                if (wb == 0) {
                    const u64* S = (const u64*)Eg;
                    const u64 M1 = F2(make_float2(-1.f, -1.f));
#pragma unroll
                    for (int v = 0; v < 8; ++v) {
                        u64 X1 = S[v * 32 + lane];
                        u64 Y1 = S[(8 + v) * 32 + lane];
                        cr2 = add2(cr2, fma2(Y[v], Y1, mul2(X[v], X1)));
                        ci2 = add2(ci2, fma2(X[v], Y1, mul2(mul2(Y[v], X1), M1)));
                        u64 n0 = fma2(Y[v], Y[v], mul2(X[v], X[v]));
                        u64 n1 = fma2(Y1, Y1, mul2(X1, X1));
                        zz2 = add2(zz2, add2(n0, mul2(n1, M1)));
                    }
                }
                break;
            case 1: meas_pack(X, Y, cr, ci, zz); break;
            case 2: meas_vbit<2>(X, Y, cr2, ci2, zz2); break;
            case 3: meas_vbit<1>(X, Y, cr2, ci2, zz2); break;
            case 4: meas_vbit<0>(X, Y, cr2, ci2, zz2); break;
            case 5: meas_lane<4>(X, Y, lane, cr2, ci2, zz2); break;
            case 6: meas_lane<3>(X, Y, lane, cr2, ci2, zz2); break;
            case 7: meas_lane<2>(X, Y, lane, cr2, ci2, zz2); break;
            case 8: meas_lane<1>(X, Y, lane, cr2, ci2, zz2); break;
            case 9: meas_lane<0>(X, Y, lane, cr2, ci2, zz2); break;
        }
        {
            float2 a = U2(cr2); cr += a.x + a.y;
            float2 bb = U2(ci2); ci += bb.x + bb.y;
            float2 cc = U2(zz2); zz += cc.x + cc.y;
        }
#pragma unroll
        for (int mm = 16; mm; mm >>= 1) {
            cr += __shfl_xor_sync(0xffffffffu, cr, mm);
            ci += __shfl_xor_sync(0xffffffffu, ci, mm);
            zz += __shfl_xor_sync(0xffffffffu, zz, mm);
        }
        if (lane == 0) {
            rsum[w * 3 + 0] = cr;
            rsum[w * 3 + 1] = ci;
            rsum[w * 3 + 2] = zz;
        }
        pairbar(barid);
        if (wb == 0 && lane == 0) {
            float crt = rsum[w * 3 + 0] + rsum[(w + 1) * 3 + 0];
            float cit = rsum[w * 3 + 1] + rsum[(w + 1) * 3 + 1];
            float zzt = rsum[w * 3 + 2] + rsum[(w + 1) * 3 + 2];
            float* outb = out + b * 30;
            outb[pair]      = 2.0f * crt;
            outb[10 + pair] = 2.0f * cit;
            outb[20 + pair] = zzt;
        }
    }
}

// ---------------------------------------------------------------------------
extern "C" void kernel_launch(void* const* d_in, const int* in_sizes, int n_in,
                              void* d_out, int out_size) {
    const float* emb    = (const float*)d_in[0];
    const float* W      = (const float*)d_in[1];
    const float* bias   = (const float*)d_in[2];
    const float* lcu_re = (const float*)d_in[3];
    const float* lcu_im = (const float*)d_in[4];
    const float* qsvt   = (const float*)d_in[5];
    const float* ffp    = (const float*)d_in[6];
    float* out = (float*)d_out;

    cudaFuncSetAttribute(quixer_kernel, cudaFuncAttributeMaxDynamicSharedMemorySize, TOT_SMEM);
    quixer_kernel<<<NB, NTHR, TOT_SMEM>>>(emb, W, bias, lcu_re, lcu_im, qsvt, ffp, out);
}

// round 13
// speedup vs baseline: 1.0881x; 1.0233x over previous
#include <cuda_runtime.h>
#include <math.h>

#define NL     32
#define NB     128
#define NPQ    40
#define NTHR   1024
#define GRP    128      // threads per barrier group (4 warps)

typedef unsigned long long u64;

// ---------------------------------------------------------------------------
// gate tables.  bit position = 9 - wire.
// type: 0 = RY (PA = bit pos), 1 = CRX (PA = control bit, PB = target bit)
// RY gates stored in TANGENT form (cs[2k] = tan(theta/2), cs[2k+1] = cos);
// prod(cos) folded into LCU weight / normalization.  CRX keep (cos, sin).
// ---------------------------------------------------------------------------
constexpr int G_TYPE[40] = {0,0,0,0,0,0,0,0,0,0, 1,1,1,1,1,1,1,1,1,1,
                            0,0,0,0,0,0,0,0,0,0, 1,1,1,1,1,1,1,1,1,1};
constexpr int G_PA[40]   = {9,8,7,6,5,4,3,2,1,0, 0,1,2,3,4,5,6,7,8,9,
                            9,8,7,6,5,4,3,2,1,0, 0,9,8,7,6,5,4,3,2,1};
constexpr int G_PB[40]   = {0,0,0,0,0,0,0,0,0,0, 9,0,1,2,3,4,5,6,7,8,
                            0,0,0,0,0,0,0,0,0,0, 1,0,9,8,7,6,5,4,3,2};

// ---------------------------------------------------------------------------
// f32x2 helpers
// ---------------------------------------------------------------------------
__device__ __forceinline__ u64 F2(float2 v) {
    u64 r; asm("mov.b64 %0, {%1,%2};" : "=l"(r) : "f"(v.x), "f"(v.y)); return r;
}
__device__ __forceinline__ float2 U2(u64 v) {
    float2 p; asm("mov.b64 {%0,%1}, %2;" : "=f"(p.x), "=f"(p.y) : "l"(v)); return p;
}
__device__ __forceinline__ u64 fma2(u64 a, u64 b, u64 c) {
    u64 d; asm("fma.rn.f32x2 %0, %1, %2, %3;" : "=l"(d) : "l"(a), "l"(b), "l"(c)); return d;
}
__device__ __forceinline__ u64 mul2(u64 a, u64 b) {
    u64 d; asm("mul.rn.f32x2 %0, %1, %2;" : "=l"(d) : "l"(a), "l"(b)); return d;
}
__device__ __forceinline__ u64 add2(u64 a, u64 b) {
    u64 d; asm("add.rn.f32x2 %0, %1, %2;" : "=l"(d) : "l"(a), "l"(b)); return d;
}
template<int M>
__device__ __forceinline__ u64 shfl2(u64 v) {
    float2 t = U2(v);
    t.x = __shfl_xor_sync(0xffffffffu, t.x, M);
    t.y = __shfl_xor_sync(0xffffffffu, t.y, M);
    return F2(t);
}
__device__ __forceinline__ u64 swap2(u64 v) {
    float2 t = U2(v);
    return F2(make_float2(t.y, t.x));
}
__device__ __forceinline__ void pairbar(int id) {
    asm volatile("bar.sync %0, 128;" :: "r"(id) : "memory");
}

// ---------------------------------------------------------------------------
// state: each PAIR of warps (w, w^1) holds one 1024-amp state.
//   amp = (wb<<9) | (pack<<8) | (v<<5) | lane ;  warp holds X[8], Y[8] u64
//   P<5 -> lane (shfl); 5<=P<8 -> v bit; P==8 -> pack (swap2); P==9 -> warp bit
// ---------------------------------------------------------------------------

// ---- RY gates, tangent form ----
template<int P>
__device__ __forceinline__ void ry_lane_t(u64 (&X)[8], u64 (&Y)[8], float t, unsigned lane) {
    const float sg = ((lane >> P) & 1u) ? t : -t;
    const u64 sg2 = F2(make_float2(sg, sg));
#pragma unroll
    for (int v = 0; v < 8; ++v) {
        X[v] = fma2(sg2, shfl2<(1 << P)>(X[v]), X[v]);
        Y[v] = fma2(sg2, shfl2<(1 << P)>(Y[v]), Y[v]);
    }
}
template<int RB>
__device__ __forceinline__ void ry_reg_t(u64 (&X)[8], u64 (&Y)[8], float t) {
    const u64 tp = F2(make_float2(t, t)), tn = F2(make_float2(-t, -t));
#pragma unroll
    for (int v0 = 0; v0 < 8; ++v0) {
        if (v0 & (1 << RB)) continue;
        const int v1 = v0 | (1 << RB);
        u64 ax0 = X[v0], ay0 = Y[v0];
        X[v0] = fma2(tn, X[v1], ax0);
        X[v1] = fma2(tp, ax0, X[v1]);
        Y[v0] = fma2(tn, Y[v1], ay0);
        Y[v1] = fma2(tp, ay0, Y[v1]);
    }
}
__device__ __forceinline__ void ry_pack_t(u64 (&X)[8], u64 (&Y)[8], float t) {
    const u64 tv = F2(make_float2(-t, t));
#pragma unroll
    for (int v = 0; v < 8; ++v) {
        X[v] = fma2(tv, swap2(X[v]), X[v]);
        Y[v] = fma2(tv, swap2(Y[v]), Y[v]);
    }
}
// RY on warp bit (tangent): smem exchange then single fma (used in layer 2)
__device__ __forceinline__ void ry_warp_t(u64 (&X)[8], u64 (&Y)[8], float t,
                                          ulonglong2* Eg, int gt, int pgt, int barid, int wb) {
#pragma unroll
    for (int i = 0; i < 4; ++i)
        Eg[i * GRP + gt] = make_ulonglong2(X[2 * i], X[2 * i + 1]);
#pragma unroll
    for (int i = 0; i < 4; ++i)
        Eg[(4 + i) * GRP + gt] = make_ulonglong2(Y[2 * i], Y[2 * i + 1]);
    pairbar(barid);
    const float sg = wb ? t : -t;
    const u64 sg2 = F2(make_float2(sg, sg));
#pragma unroll
    for (int i = 0; i < 4; ++i) {
        ulonglong2 p = Eg[i * GRP + pgt];
        X[2 * i]     = fma2(sg2, p.x, X[2 * i]);
        X[2 * i + 1] = fma2(sg2, p.y, X[2 * i + 1]);
    }
#pragma unroll
    for (int i = 0; i < 4; ++i) {
        ulonglong2 p = Eg[(4 + i) * GRP + pgt];
        Y[2 * i]     = fma2(sg2, p.x, Y[2 * i]);
        Y[2 * i + 1] = fma2(sg2, p.y, Y[2 * i + 1]);
    }
    pairbar(barid);
}

// FUSED gate: RY(bit9, tangent t) followed by CRX(control lane-bit0 -> target bit9; c,s)
// new = alpha*mine + beta*partner  (complex alpha, beta per (lane&1, wb))
//   even lanes:  alpha = 1,           beta = (wb ? t : -t)
//   odd  lanes:  wb=0: alpha = c - i s t,  beta = -c t - i s
//                wb=1: alpha = c + i s t,  beta =  c t - i s
__device__ __forceinline__ void fused_ry9_crx09(u64 (&X)[8], u64 (&Y)[8],
                                                float t, float c, float s, unsigned lane,
                                                ulonglong2* Eg, int gt, int pgt,
                                                int barid, int wb) {
#pragma unroll
    for (int i = 0; i < 4; ++i)
        Eg[i * GRP + gt] = make_ulonglong2(X[2 * i], X[2 * i + 1]);
#pragma unroll
    for (int i = 0; i < 4; ++i)
        Eg[(4 + i) * GRP + gt] = make_ulonglong2(Y[2 * i], Y[2 * i + 1]);
    pairbar(barid);
    const int b0 = lane & 1;
    const float wsg = wb ? 1.f : -1.f;
    const float ar = b0 ? c : 1.f;
    const float ai = b0 ? wsg * s * t : 0.f;
    const float br = b0 ? wsg * c * t : wsg * t;
    const float bi = b0 ? -s : 0.f;
    const u64 ar2 = F2(make_float2(ar, ar));
    const u64 ai2 = F2(make_float2(ai, ai)), nai2 = F2(make_float2(-ai, -ai));
    const u64 br2 = F2(make_float2(br, br));
    const u64 bi2 = F2(make_float2(bi, bi)), nbi2 = F2(make_float2(-bi, -bi));
#pragma unroll
    for (int i = 0; i < 4; ++i) {
        ulonglong2 px = Eg[i * GRP + pgt];
        ulonglong2 py = Eg[(4 + i) * GRP + pgt];
        u64 x0 = X[2 * i], x1 = X[2 * i + 1];
        u64 y0 = Y[2 * i], y1 = Y[2 * i + 1];
        X[2 * i]     = fma2(nbi2, py.x, fma2(br2, px.x, fma2(nai2, y0, mul2(ar2, x0))));
        X[2 * i + 1] = fma2(nbi2, py.y, fma2(br2, px.y, fma2(nai2, y1, mul2(ar2, x1))));
        Y[2 * i]     = fma2(bi2, px.x, fma2(br2, py.x, fma2(ai2, x0, mul2(ar2, y0))));
        Y[2 * i + 1] = fma2(bi2, px.y, fma2(br2, py.y, fma2(ai2, x1, mul2(ar2, y1))));
    }
    pairbar(barid);
}

// CRX k=10 with Y==0 everywhere (step-1 fast path): exchange X only.
__device__ __forceinline__ void crx10_y0(u64 (&X)[8], u64 (&Y)[8], float c, float s,
                                         unsigned lane, ulonglong2* Eg, int gt, int pgt, int barid) {
    const bool act = (lane & 1u) != 0u;
    if (act) {
#pragma unroll
        for (int i = 0; i < 4; ++i)
            Eg[i * GRP + gt] = make_ulonglong2(X[2 * i], X[2 * i + 1]);
    }
    pairbar(barid);
    if (act) {
        const u64 cc = F2(make_float2(c, c));
        const u64 sn = F2(make_float2(-s, -s));
#pragma unroll
        for (int i = 0; i < 4; ++i) {
            ulonglong2 px = Eg[i * GRP + pgt];
            Y[2 * i]     = mul2(sn, px.x);
            Y[2 * i + 1] = mul2(sn, px.y);
            X[2 * i]     = mul2(cc, X[2 * i]);
            X[2 * i + 1] = mul2(cc, X[2 * i + 1]);
        }
    }
    pairbar(barid);
}
// CRX k=32: control = pack bit (hi half), target = warp bit.  Exchange hi floats only.
__device__ __forceinline__ void crx32(u64 (&X)[8], u64 (&Y)[8], float c, float s,
                                      float* Fg, int gt, int pgt, int barid) {
#pragma unroll
    for (int i = 0; i < 8; ++i) Fg[i * GRP + gt] = U2(X[i]).y;
#pragma unroll
    for (int i = 0; i < 8; ++i) Fg[(8 + i) * GRP + gt] = U2(Y[i]).y;
    pairbar(barid);
#pragma unroll
    for (int i = 0; i < 8; ++i) {
        float pxh = Fg[i * GRP + pgt];
        float pyh = Fg[(8 + i) * GRP + pgt];
        float2 x = U2(X[i]), y = U2(Y[i]);
        x.y = fmaf(s, pyh, c * x.y);
        y.y = fmaf(-s, pxh, c * y.y);
        X[i] = F2(x); Y[i] = F2(y);
    }
    pairbar(barid);
}

// RX (warp-bit-controlled, executes locally on wb==1) on target B != 9
template<int B>
__device__ __forceinline__ void rx_local(u64 (&X)[8], u64 (&Y)[8], float c, float s) {
    const u64 ce2 = F2(make_float2(c, c));
    const u64 se2 = F2(make_float2(s, s)), sn2 = F2(make_float2(-s, -s));
    if constexpr (B < 5) {
#pragma unroll
        for (int v = 0; v < 8; ++v) {
            u64 px = shfl2<(1 << B)>(X[v]);
            u64 py = shfl2<(1 << B)>(Y[v]);
            X[v] = fma2(se2, py, mul2(ce2, X[v]));
            Y[v] = fma2(sn2, px, mul2(ce2, Y[v]));
        }
    } else if constexpr (B < 8) {
        constexpr int TB = 1 << (B - 5);
#pragma unroll
        for (int v0 = 0; v0 < 8; ++v0) {
            if (v0 & TB) continue;
            const int v1 = v0 | TB;
            u64 a0x = X[v0], a0y = Y[v0], a1x = X[v1], a1y = Y[v1];
            X[v0] = fma2(se2, a1y, mul2(ce2, a0x));
            Y[v0] = fma2(sn2, a1x, mul2(ce2, a0y));
            X[v1] = fma2(se2, a0y, mul2(ce2, a1x));
            Y[v1] = fma2(sn2, a0x, mul2(ce2, a1y));
        }
    } else {
#pragma unroll
        for (int v = 0; v < 8; ++v) {
            u64 sx = swap2(X[v]), sy = swap2(Y[v]);
            X[v] = fma2(se2, sy, mul2(ce2, X[v]));
            Y[v] = fma2(sn2, sx, mul2(ce2, Y[v]));
        }
    }
}

// CRX, control A != 9, target B != 9
template<int A, int B>
__device__ __forceinline__ void crx_gate(u64 (&X)[8], u64 (&Y)[8], float c, float s, unsigned lane) {
    float2 cef, sef;
    if constexpr (A < 5) {
        const int cb = (lane >> A) & 1u;
        const float ce = cb ? c : 1.0f, se = cb ? s : 0.0f;
        cef = make_float2(ce, ce); sef = make_float2(se, se);
    } else if constexpr (A == 8) {
        cef = make_float2(1.0f, c); sef = make_float2(0.0f, s);
    } else {
        cef = make_float2(c, c); sef = make_float2(s, s);
    }
    const u64 ce2 = F2(cef), se2 = F2(sef), sn2 = F2(make_float2(-sef.x, -sef.y));
    constexpr bool vctrl = (A >= 5 && A < 8);
    constexpr int CB = vctrl ? (1 << (A - 5)) : 0;

    if constexpr (B < 5) {
#pragma unroll
        for (int v = 0; v < 8; ++v) {
            if (vctrl && !(v & CB)) continue;
            u64 px = shfl2<(1 << B)>(X[v]);
            u64 py = shfl2<(1 << B)>(Y[v]);
            X[v] = fma2(se2, py, mul2(ce2, X[v]));
            Y[v] = fma2(sn2, px, mul2(ce2, Y[v]));
        }
    } else if constexpr (B < 8) {
        constexpr int TB = 1 << (B - 5);
#pragma unroll
        for (int v0 = 0; v0 < 8; ++v0) {
            if (v0 & TB) continue;
            if (vctrl && !(v0 & CB)) continue;
            const int v1 = v0 | TB;
            u64 a0x = X[v0], a0y = Y[v0], a1x = X[v1], a1y = Y[v1];
            X[v0] = fma2(se2, a1y, mul2(ce2, a0x));
            Y[v0] = fma2(sn2, a1x, mul2(ce2, a0y));
            X[v1] = fma2(se2, a0y, mul2(ce2, a1x));
            Y[v1] = fma2(sn2, a0x, mul2(ce2, a1y));
        }
    } else {
#pragma unroll
        for (int v = 0; v < 8; ++v) {
            if (vctrl && !(v & CB)) continue;
            u64 sx = swap2(X[v]), sy = swap2(Y[v]);
            X[v] = fma2(se2, sy, mul2(ce2, X[v]));
            Y[v] = fma2(sn2, sx, mul2(ce2, Y[v]));
        }
    }
}

template<int K>
__device__ __forceinline__ void do_gate(u64 (&X)[8], u64 (&Y)[8], const float* csl,
                                        unsigned lane, int wb,
                                        ulonglong2* Eg, float* Fg, int gt, int pgt, int barid) {
    const float c = csl[2 * K];          // t for RY gates, cos for CRX gates
    const float s = csl[2 * K + 1];
    constexpr int A = G_PA[K], Bp = G_PB[K];
    if constexpr (K == 20) {
        ry_warp_t(X, Y, c, Eg, gt, pgt, barid, wb);
    } else if constexpr (K == 32) {
        crx32(X, Y, c, s, Fg, gt, pgt, barid);
    } else if constexpr (G_TYPE[K] == 1 && A == 9) {
        if (wb) rx_local<Bp>(X, Y, c, s);
    } else if constexpr (G_TYPE[K] == 0) {
        if constexpr (A == 8)      ry_pack_t(X, Y, c);
        else if constexpr (A >= 5) ry_reg_t<A - 5>(X, Y, c);
        else                       ry_lane_t<A>(X, Y, c, lane);
    } else {
        crx_gate<A, Bp>(X, Y, c, s, lane);
    }
}

template<int K, int KEND = 40>
__device__ __forceinline__ void run_gates(u64 (&X)[8], u64 (&Y)[8], const float* csl,
                                          unsigned lane, int wb,
                                          ulonglong2* Eg, float* Fg, int gt, int pgt, int barid) {
    if constexpr (K < KEND) {
        do_gate<K>(X, Y, csl, lane, wb, Eg, Fg, gt, pgt, barid);
        run_gates<K + 1, KEND>(X, Y, csl, lane, wb, Eg, Fg, gt, pgt, barid);
    }
}

// full run with layer-1 reordering: RY k=1..9, then fused(RY9 + CRX(0->9)), then k=11..
__device__ __forceinline__ void run_full(u64 (&X)[8], u64 (&Y)[8], const float* csl,
                                         unsigned lane, int wb,
                                         ulonglong2* Eg, float* Fg, int gt, int pgt, int barid) {
    run_gates<1, 10>(X, Y, csl, lane, wb, Eg, Fg, gt, pgt, barid);
    fused_ry9_crx09(X, Y, csl[0], csl[20], csl[21], lane, Eg, gt, pgt, barid, wb);
    run_gates<11, 40>(X, Y, csl, lane, wb, Eg, Fg, gt, pgt, barid);
}

// ---- step-1 shortcut: product state after first RY layer, tangent form ----
__device__ __forceinline__ void build_ry_product(u64 (&X)[8], u64 (&Y)[8],
                                                 const float* cs, unsigned lane, int wb) {
    float A = wb ? cs[0] : 1.0f;                       // P=9, k=0
    A *= (lane & 1u)  ? cs[18] : 1.0f;                 // P=0, k=9
    A *= (lane & 2u)  ? cs[16] : 1.0f;                 // P=1, k=8
    A *= (lane & 4u)  ? cs[14] : 1.0f;                 // P=2, k=7
    A *= (lane & 8u)  ? cs[12] : 1.0f;                 // P=3, k=6
    A *= (lane & 16u) ? cs[10] : 1.0f;                 // P=4, k=5
    const float t4 = cs[8], t3 = cs[6], t2 = cs[4], t1 = cs[2];
    float fv[8];
    fv[0] = 1.f;     fv[1] = t4;      fv[2] = t3;      fv[3] = t4 * t3;
    fv[4] = t2;      fv[5] = t4 * t2; fv[6] = t3 * t2; fv[7] = t4 * t3 * t2;
#pragma unroll
    for (int v = 0; v < 8; ++v) {
        const float g = A * fv[v];
        X[v] = F2(make_float2(g, g * t1));
        Y[v] = 0ull;
    }
}

// ---- register-resident measurement helpers (wire = pair, P = 9-pair) ----
template<int P>
__device__ __forceinline__ void meas_lane(const u64 (&X)[8], const u64 (&Y)[8], unsigned lane,
                                          u64& cr2, u64& ci2, u64& zz2) {
    const int bit = (lane >> P) & 1u;
    const u64 f02 = F2(bit ? make_float2(0.f, 0.f) : make_float2(1.f, 1.f));
    const u64 zs2 = F2(bit ? make_float2(-1.f, -1.f) : make_float2(1.f, 1.f));
    const u64 M1  = F2(make_float2(-1.f, -1.f));
#pragma unroll
    for (int v = 0; v < 8; ++v) {
        u64 px = shfl2<(1 << P)>(X[v]);
        u64 py = shfl2<(1 << P)>(Y[v]);
        u64 t1 = fma2(Y[v], py, mul2(X[v], px));
        cr2 = fma2(f02, t1, cr2);
        u64 t2 = fma2(X[v], py, mul2(mul2(Y[v], px), M1));
        ci2 = fma2(f02, t2, ci2);
        u64 nn = fma2(Y[v], Y[v], mul2(X[v], X[v]));
        zz2 = fma2(zs2, nn, zz2);
    }
}
template<int RB>
__device__ __forceinline__ void meas_vbit(const u64 (&X)[8], const u64 (&Y)[8],
                                          u64& cr2, u64& ci2, u64& zz2) {
    const u64 M1 = F2(make_float2(-1.f, -1.f));
#pragma unroll
    for (int v0 = 0; v0 < 8; ++v0) {
        if (v0 & (1 << RB)) continue;
        const int v1 = v0 | (1 << RB);
        cr2 = add2(cr2, fma2(Y[v0], Y[v1], mul2(X[v0], X[v1])));
        ci2 = add2(ci2, fma2(X[v0], Y[v1], mul2(mul2(Y[v0], X[v1]), M1)));
        u64 n0 = fma2(Y[v0], Y[v0], mul2(X[v0], X[v0]));
        u64 n1 = fma2(Y[v1], Y[v1], mul2(X[v1], X[v1]));
        zz2 = add2(zz2, add2(n0, mul2(n1, M1)));
    }
}
__device__ __forceinline__ void meas_pack(const u64 (&X)[8], const u64 (&Y)[8],
                                          float& cr, float& ci, float& zz) {
#pragma unroll
    for (int v = 0; v < 8; ++v) {
        float2 x = U2(X[v]), y = U2(Y[v]);
        cr += x.x * x.y + y.x * y.y;
        ci += x.x * y.y - y.x * x.y;
        zz += (x.x * x.x + y.x * y.x) - (x.y * x.y + y.y * y.y);
    }
}

// ---------------------------------------------------------------------------
// smem layout (bytes):
//   [0,10240)      cs_s   2560 f
//   [10240,10560)  ffcs   80 f
//   [10560,10816)  lcu_s  32 f2
//   [10816,11072)  rsum   64 f
//   [11072,11584)  cscale 128 f (64 used)
//   [11584,11600)  sff    4 f (1 used)
//   [11600, ...)   UNION:
//     GEMM:  emb_s 32*516 f (66048) | W_s 40*512 f (81920)   = 147968
//     MAIN:  buf 16384 u64 (131072) | cur 1024 u64 (8192)    = 139264
// ---------------------------------------------------------------------------
#define OFF_UNION  11600
#define TOT_SMEM   (OFF_UNION + 147968)

__global__ void __launch_bounds__(NTHR, 1)
quixer_kernel(const float* __restrict__ emb, const float* __restrict__ W,
              const float* __restrict__ bias,
              const float* __restrict__ lcu_re, const float* __restrict__ lcu_im,
              const float* __restrict__ qsvt, const float* __restrict__ ffp,
              float* __restrict__ out) {
    extern __shared__ char smraw[];
    float*  cs_s   = (float*)smraw;                      // 2560 f
    float*  ffcs   = cs_s + 2560;                        // 80 f
    float2* lcu_s  = (float2*)(ffcs + 80);               // 32 f2
    float*  rsum   = (float*)(lcu_s + 32);               // 64 f
    float*  cscale = rsum + 64;                          // 128 f
    float*  sff    = cscale + 128;                       // 1 f
    char*   un     = smraw + OFF_UNION;
    float*  emb_s  = (float*)un;                         // 32*516
    float*  W_s    = emb_s + 32 * 516;                   // 40*512
    u64*    buf    = (u64*)un;                           // 16*1024 u64
    u64*    cur    = buf + 16 * 1024;                    // 1024 u64

    const int b   = blockIdx.x;
    const int tid = threadIdx.x;
    const int w   = tid >> 5;
    const unsigned lane = tid & 31u;
    const int wb    = w & 1;
    const int pair  = w >> 1;
    const int grp   = w >> 2;
    const int gt    = tid & (GRP - 1);
    const int pgt   = gt ^ 32;
    const int barid = 1 + grp;
    ulonglong2* Eg  = (ulonglong2*)buf + grp * 1024;
    float*      Fg  = (float*)Eg;

    // ---------------- phase 1: GEMM + trig ----------------
    {
        const float4* embg   = (const float4*)(emb + (size_t)b * 32 * 512);
        float4*       emb_s4 = (float4*)emb_s;
        for (int i = tid; i < 4096; i += NTHR) {
            int l = i >> 7, d4 = i & 127;
            emb_s4[l * 129 + d4] = embg[i];
        }
        const float4* Wg   = (const float4*)W;
        float4*       W_s4 = (float4*)W_s;
        for (int i = tid; i < 5120; i += NTHR) W_s4[i] = Wg[i];
    }

    if (tid < 40) {
        float sv, cv;
        __sincosf(0.5f * ffp[tid], &sv, &cv);
        const bool isRY = (tid < 10) || (tid >= 20 && tid < 30);
        if (isRY) {
            ffcs[2 * tid]     = __fdividef(sv, cv);      // tangent
            ffcs[2 * tid + 1] = cv;
        } else {
            ffcs[2 * tid]     = cv;
            ffcs[2 * tid + 1] = sv;
        }
    }
    if (w == 1) {
        float re = lcu_re[lane], im = lcu_im[lane];
        float S = sqrtf(re * re + im * im);
#pragma unroll
        for (int m = 16; m; m >>= 1) S += __shfl_xor_sync(0xffffffffu, S, m);
        lcu_s[lane] = make_float2(re / S, im / S);
    }
    __syncthreads();

    // GEMM: 128 threads, thread = (l, kg of 10 k's), f32x2 accumulate.
    if (tid < 128) {
        const int l  = tid & 31;
        const int kg = tid >> 5;             // 0..3
        u64 acc10[10];
#pragma unroll
        for (int j = 0; j < 10; ++j) acc10[j] = 0ull;
        const float4* er = (const float4*)emb_s + l * 129;
        const float4* wr = (const float4*)W_s + kg * 10 * 128;
#pragma unroll 2
        for (int d = 0; d < 128; ++d) {
            float4 a = er[d];
            u64 alo = F2(make_float2(a.x, a.y));
            u64 ahi = F2(make_float2(a.z, a.w));
#pragma unroll
            for (int j = 0; j < 10; ++j) {
                float4 wv = wr[j * 128 + d];
                acc10[j] = fma2(alo, F2(make_float2(wv.x, wv.y)), acc10[j]);
                acc10[j] = fma2(ahi, F2(make_float2(wv.z, wv.w)), acc10[j]);
            }
        }
        const bool ryg = (kg == 0) || (kg == 2);   // k 0..9 and 20..29 are RY
        float p10 = 1.0f;
#pragma unroll
        for (int j = 0; j < 10; ++j) {
            int k = kg * 10 + j;
            float2 av = U2(acc10[j]);
            float th = 0.5f * (av.x + av.y + bias[k]);
            float sv, cv;
            __sincosf(th, &sv, &cv);
            if (ryg) {
                cs_s[l * 80 + 2 * k]     = __fdividef(sv, cv);
                cs_s[l * 80 + 2 * k + 1] = cv;
                p10 *= cv;
            } else {
                cs_s[l * 80 + 2 * k]     = cv;
                cs_s[l * 80 + 2 * k + 1] = sv;
            }
        }
        if (ryg) cscale[l * 2 + (kg >> 1)] = p10;
    }
    __syncthreads();

    // fold prod(cos) into lcu weights; compute ff scale
    if (tid < 32) {
        float S = cscale[tid * 2] * cscale[tid * 2 + 1];
        float2 lw = lcu_s[tid];
        lcu_s[tid] = make_float2(lw.x * S, lw.y * S);
    }
    if (tid == 33) {
        float S = 1.0f;
#pragma unroll
        for (int k = 0; k < 10; ++k)  S *= ffcs[2 * k + 1];
#pragma unroll
        for (int k = 20; k < 30; ++k) S *= ffcs[2 * k + 1];
        sff[0] = S;
    }
    __syncthreads();   // cs/lcu/sff ready; union region free for buf/cur

    // ---------------- phase 2: QSVT mainloop ----------------
    const float q0 = qsvt[0], q1 = qsvt[1], q2 = qsvt[2];
    u64 acc = (tid == 0) ? F2(make_float2(q0, 0.f)) : 0ull;

    u64 X[8], Y[8];
    const int wbp = tid >> 9;
    const int r   = tid & 511;

    for (int step = 1; step <= 2; ++step) {
        const float qk = (step == 1) ? q1 : q2;
        u64 m = 0ull;
        for (int pass = 0; pass < 2; ++pass) {
            const int l = pair + pass * 16;
            const float* csl = cs_s + l * 80;
            if (step == 1) {
                build_ry_product(X, Y, csl, lane, wb);
                crx10_y0(X, Y, csl[20], csl[21], lane, Eg, gt, pgt, barid);
                run_gates<11>(X, Y, csl, lane, wb, Eg, Fg, gt, pgt, barid);
            } else {
#pragma unroll
                for (int v = 0; v < 8; ++v) {
                    X[v] = cur[wb * 512 + v * 32 + lane];
                    Y[v] = cur[wb * 512 + 256 + v * 32 + lane];
                }
                run_full(X, Y, csl, lane, wb, Eg, Fg, gt, pgt, barid);
            }
            // complex LCU scale (includes folded prod-cos)
            const float2 lw = lcu_s[l];
            const u64 av = F2(make_float2(lw.x, lw.x));
            const u64 bp = F2(make_float2(lw.y, lw.y));
            const u64 bn = F2(make_float2(-lw.y, -lw.y));
#pragma unroll
            for (int v = 0; v < 8; ++v) {
                u64 tx = X[v];
                X[v] = fma2(bn, Y[v], mul2(av, tx));
                Y[v] = fma2(bp, tx, mul2(av, Y[v]));
            }
            // stage to buf
            u64* rw = buf + w * 512;
#pragma unroll
            for (int v = 0; v < 8; ++v) {
                rw[v * 32 + lane]       = X[v];
                rw[256 + v * 32 + lane] = Y[v];
            }
            __syncthreads();
            // flat 16-way sum over pairs
            u64 a0 = buf[wbp * 512 + r];
            u64 a1 = buf[(2 + wbp) * 512 + r];
#pragma unroll
            for (int p = 2; p < 16; p += 2) {
                a0 = add2(a0, buf[(2 * p + wbp) * 512 + r]);
                a1 = add2(a1, buf[(2 * p + 2 + wbp) * 512 + r]);
            }
            u64 a = add2(a0, a1);
            m = (pass == 0) ? a : add2(m, a);
            if (pass == 0) __syncthreads();
        }
        const u64 qk2 = F2(make_float2(qk, qk));
        acc = fma2(qk2, m, acc);
        if (step == 1) {
            cur[tid] = m;
            __syncthreads();
        }
    }

    // normalize acc
    {
        float2 t0 = U2(acc);
        float p = t0.x * t0.x + t0.y * t0.y;
#pragma unroll
        for (int mm = 16; mm; mm >>= 1) p += __shfl_xor_sync(0xffffffffu, p, mm);
        if (lane == 0) rsum[w] = p;
    }
    __syncthreads();
    if (tid == 0) {
        float t = 0.f;
#pragma unroll
        for (int i = 0; i < 32; ++i) t += rsum[i];
        rsum[0] = rsqrtf(t) * sff[0];
    }
    __syncthreads();
    {
        const float inv = rsum[0];
        cur[tid] = mul2(acc, F2(make_float2(inv, inv)));
    }
    __syncthreads();

    // feed-forward PQC: ALL pairs compute redundantly
#pragma unroll
    for (int v = 0; v < 8; ++v) {
        X[v] = cur[wb * 512 + v * 32 + lane];
        Y[v] = cur[wb * 512 + 256 + v * 32 + lane];
    }
    run_full(X, Y, ffcs, lane, wb, Eg, Fg, gt, pgt, barid);

    // measurement: pair p measures wire p from registers
    if (w < 20) {
        u64 cr2 = 0ull, ci2 = 0ull, zz2 = 0ull;
        float cr = 0.f, ci = 0.f, zz = 0.f;

        if (pair == 0 && wb == 1) {
            u64* S = (u64*)Eg;
#pragma unroll
            for (int v = 0; v < 8; ++v) {
                S[v * 32 + lane]       = X[v];
                S[(8 + v) * 32 + lane] = Y[v];
            }
        }
        if (grp == 0) pairbar(1);

        switch (pair) {
            case 0:
                if (wb == 0) {
                    const u64* S = (const u64*)Eg;
                    const u64 M1 = F2(make_float2(-1.f, -1.f));
#pragma unroll
                    for (int v = 0; v < 8; ++v) {
                        u64 X1 = S[v * 32 + lane];
                        u64 Y1 = S[(8 + v) * 32 + lane];
                        cr2 = add2(cr2, fma2(Y[v], Y1, mul2(X[v], X1)));
                        ci2 = add2(ci2, fma2(X[v], Y1, mul2(mul2(Y[v], X1), M1)));
                        u64 n0 = fma2(Y[v], Y[v], mul2(X[v], X[v]));
                        u64 n1 = fma2(Y1, Y1, mul2(X1, X1));
                        zz2 = add2(zz2, add2(n0, mul2(n1, M1)));
                    }
                }
                break;
            case 1: meas_pack(X, Y, cr, ci, zz); break;
            case 2: meas_vbit<2>(X, Y, cr2, ci2, zz2); break;
            case 3: meas_vbit<1>(X, Y, cr2, ci2, zz2); break;
            case 4: meas_vbit<0>(X, Y, cr2, ci2, zz2); break;
            case 5: meas_lane<4>(X, Y, lane, cr2, ci2, zz2); break;
            case 6: meas_lane<3>(X, Y, lane, cr2, ci2, zz2); break;
            case 7: meas_lane<2>(X, Y, lane, cr2, ci2, zz2); break;
            case 8: meas_lane<1>(X, Y, lane, cr2, ci2, zz2); break;
            case 9: meas_lane<0>(X, Y, lane, cr2, ci2, zz2); break;
        }
        {
            float2 a = U2(cr2); cr += a.x + a.y;
            float2 bb = U2(ci2); ci += bb.x + bb.y;
            float2 cc = U2(zz2); zz += cc.x + cc.y;
        }
#pragma unroll
        for (int mm = 16; mm; mm >>= 1) {
            cr += __shfl_xor_sync(0xffffffffu, cr, mm);
            ci += __shfl_xor_sync(0xffffffffu, ci, mm);
            zz += __shfl_xor_sync(0xffffffffu, zz, mm);
        }
        if (lane == 0) {
            rsum[w * 3 + 0] = cr;
            rsum[w * 3 + 1] = ci;
            rsum[w * 3 + 2] = zz;
        }
        pairbar(barid);
        if (wb == 0 && lane == 0) {
            float crt = rsum[w * 3 + 0] + rsum[(w + 1) * 3 + 0];
            float cit = rsum[w * 3 + 1] + rsum[(w + 1) * 3 + 1];
            float zzt = rsum[w * 3 + 2] + rsum[(w + 1) * 3 + 2];
            float* outb = out + b * 30;
            outb[pair]      = 2.0f * crt;
            outb[10 + pair] = 2.0f * cit;
            outb[20 + pair] = zzt;
        }
    }
}

// ---------------------------------------------------------------------------
extern "C" void kernel_launch(void* const* d_in, const int* in_sizes, int n_in,
                              void* d_out, int out_size) {
    const float* emb    = (const float*)d_in[0];
    const float* W      = (const float*)d_in[1];
    const float* bias   = (const float*)d_in[2];
    const float* lcu_re = (const float*)d_in[3];
    const float* lcu_im = (const float*)d_in[4];
    const float* qsvt   = (const float*)d_in[5];
    const float* ffp    = (const float*)d_in[6];
    float* out = (float*)d_out;

    cudaFuncSetAttribute(quixer_kernel, cudaFuncAttributeMaxDynamicSharedMemorySize, TOT_SMEM);
    quixer_kernel<<<NB, NTHR, TOT_SMEM>>>(emb, W, bias, lcu_re, lcu_im, qsvt, ffp, out);
}